// round 2
// baseline (speedup 1.0000x reference)
#include <cuda_runtime.h>
#include <math.h>

// Problem constants
#define NF   128          // frames
#define PP   576          // patches
#define DD   1536         // feature dim
#define LMq  4096         // LM
#define NQk  64           // NQ
#define NM1  127          // N-1
#define NC   8            // NUM_CUBES

// Scratch layout (no allocations allowed)
#define OFF_MP    0                       // [2][NF][DD] patch-sum halves
#define OFF_EMA   (2*NF*DD)
#define OFF_FEAT  (OFF_EMA  + NM1*DD)
#define OFF_XN    (OFF_FEAT + NM1*DD)
#define OFF_H     (OFF_XN   + NM1*DD)
#define OFF_POOL  (OFF_H    + NM1*DD)
#define OFF_Y     (OFF_POOL + NQk*DD)
#define SCRATCH_TOTAL (OFF_Y + 256)

__device__ float g_scratch[SCRATCH_TOTAL];
__device__ int   g_sel[NC + 1];

// ---------------------------------------------------------------------------
// Kernel 1: patch sums, patch dim split in 2 for occupancy/MLP.
// grid = NF*3*2 blocks, 128 threads, float4 per thread (512 d per block).
// mp2[h][n][d] = sum over 288 patches.
// ---------------------------------------------------------------------------
__global__ void k_mp(const float* __restrict__ v, float* __restrict__ mp2) {
    int b = blockIdx.x;
    int hh = b & 1;
    int nc = b >> 1;
    int n = nc / 3, c = nc % 3;
    int d = c * 512 + threadIdx.x * 4;
    const float* base = v + (size_t)n * PP * DD + (size_t)hh * 288 * DD + d;
    float ax = 0.f, ay = 0.f, az = 0.f, aw = 0.f;
#pragma unroll 8
    for (int p = 0; p < 288; p++) {
        float4 x = *reinterpret_cast<const float4*>(base + (size_t)p * DD);
        ax += x.x; ay += x.y; az += x.z; aw += x.w;
    }
    float4 r = make_float4(ax, ay, az, aw);
    *reinterpret_cast<float4*>(&mp2[(size_t)hh * NF * DD + (size_t)n * DD + d]) = r;
}

// ---------------------------------------------------------------------------
// Kernel 2: combine halves -> patch mean, then momentum EMA scan per d.
// ---------------------------------------------------------------------------
__global__ void k_ema(const float* __restrict__ mp2, float* __restrict__ ema) {
    int d = blockIdx.x * blockDim.x + threadIdx.x;
    const float inv = 1.0f / (float)PP;
    float prev = (mp2[d] + mp2[(size_t)NF * DD + d]) * inv;
    float e = 0.f;
    for (int i = 1; i < NF; i++) {
        float cur = (mp2[(size_t)i * DD + d] + mp2[(size_t)(NF + i) * DD + d]) * inv;
        float diff = cur - prev;
        e = (i == 1) ? diff : (0.5f * diff + 0.5f * e);
        ema[(size_t)(i - 1) * DD + d] = e;
        prev = cur;
    }
}

// ---------------------------------------------------------------------------
// Bias init:  C[m, n] = bias[n]
// ---------------------------------------------------------------------------
__global__ void k_init_bias(float* __restrict__ C, const float* __restrict__ bias,
                            int total, int Nn) {
    int idx = blockIdx.x * blockDim.x + threadIdx.x;
    if (idx < total) C[idx] = bias[idx % Nn];
}

// ---------------------------------------------------------------------------
// Split-K GEMM with packed fma.rn.f32x2 (2 fp32 FMA per issue, exact IEEE).
// C += A[M,K] @ B[K,N]. Tile 64x64, BK=16, 128 threads, 8m x 4n micro-tile
// accumulated as 4 m-pairs (b64). B duplicated in smem so {b,b} is one LDS.64.
// grid(N/64, ceil(M/64), S); Kc multiple of 16.
// ---------------------------------------------------------------------------
__global__ void k_gemm_f2(const float* __restrict__ A, const float* __restrict__ B,
                          float* __restrict__ C, int M, int Nn, int K, int Kc) {
    __shared__ __align__(16) float As[16][66];    // [k][m]
    __shared__ __align__(16) float Bsd[16][130];  // [k][2*n] duplicated pairs
    const int n0 = blockIdx.x * 64;
    const int m0 = blockIdx.y * 64;
    const int k0 = blockIdx.z * Kc;
    const int tid = threadIdx.x;
    const int tx = tid & 15, ty = tid >> 4;

    unsigned long long acc[4][4];
#pragma unroll
    for (int i = 0; i < 4; i++)
#pragma unroll
        for (int j = 0; j < 4; j++) acc[i][j] = 0ull;

    const int a_ml = tid >> 1;           // m within tile (0..63)
    const int a_ks = (tid & 1) * 8;      // k segment (0 or 8)
    const int b_kl = tid >> 3;           // k row (0..15)
    const int b_ns = (tid & 7) * 8;      // n segment (0..56)
    const int a_m = m0 + a_ml;
    const float* aptr = A + (size_t)a_m * K + a_ks;
    const float* bptr = B + (size_t)b_kl * Nn + n0 + b_ns;

    for (int kb = k0; kb < k0 + Kc; kb += 16) {
        float4 x0, x1;
        if (a_m < M) {
            x0 = *reinterpret_cast<const float4*>(aptr + kb);
            x1 = *reinterpret_cast<const float4*>(aptr + kb + 4);
        } else {
            x0 = make_float4(0.f, 0.f, 0.f, 0.f); x1 = x0;
        }
        float4 y0 = *reinterpret_cast<const float4*>(bptr + (size_t)kb * Nn);
        float4 y1 = *reinterpret_cast<const float4*>(bptr + (size_t)kb * Nn + 4);

        As[a_ks + 0][a_ml] = x0.x; As[a_ks + 1][a_ml] = x0.y;
        As[a_ks + 2][a_ml] = x0.z; As[a_ks + 3][a_ml] = x0.w;
        As[a_ks + 4][a_ml] = x1.x; As[a_ks + 5][a_ml] = x1.y;
        As[a_ks + 6][a_ml] = x1.z; As[a_ks + 7][a_ml] = x1.w;

        float2* bd = reinterpret_cast<float2*>(&Bsd[b_kl][b_ns * 2]);
        bd[0] = make_float2(y0.x, y0.x); bd[1] = make_float2(y0.y, y0.y);
        bd[2] = make_float2(y0.z, y0.z); bd[3] = make_float2(y0.w, y0.w);
        bd[4] = make_float2(y1.x, y1.x); bd[5] = make_float2(y1.y, y1.y);
        bd[6] = make_float2(y1.z, y1.z); bd[7] = make_float2(y1.w, y1.w);
        __syncthreads();

#pragma unroll
        for (int kk = 0; kk < 16; kk++) {
            unsigned long long av[4], bv[4];
#pragma unroll
            for (int i = 0; i < 4; i++)
                av[i] = *reinterpret_cast<const unsigned long long*>(&As[kk][ty * 8 + 2 * i]);
#pragma unroll
            for (int j = 0; j < 4; j++)
                bv[j] = *reinterpret_cast<const unsigned long long*>(&Bsd[kk][(tx * 4 + j) * 2]);
#pragma unroll
            for (int i = 0; i < 4; i++)
#pragma unroll
                for (int j = 0; j < 4; j++)
                    asm("fma.rn.f32x2 %0, %1, %2, %0;"
                        : "+l"(acc[i][j]) : "l"(av[i]), "l"(bv[j]));
        }
        __syncthreads();
    }

#pragma unroll
    for (int i = 0; i < 4; i++) {
        int mA = m0 + ty * 8 + 2 * i;
#pragma unroll
        for (int j = 0; j < 4; j++) {
            unsigned long long p = acc[i][j];
            float lo = __uint_as_float((unsigned)(p & 0xffffffffull));
            float hi = __uint_as_float((unsigned)(p >> 32));
            int n = n0 + tx * 4 + j;
            if (mA < M)     atomicAdd(&C[(size_t)mA * Nn + n], lo);
            if (mA + 1 < M) atomicAdd(&C[(size_t)(mA + 1) * Nn + n], hi);
        }
    }
}

// ---------------------------------------------------------------------------
// LayerNorm per row (two-pass)
// ---------------------------------------------------------------------------
__global__ void k_ln(const float* __restrict__ X, float* __restrict__ Y,
                     const float* __restrict__ gam, const float* __restrict__ bet) {
    int m = blockIdx.x;
    const float* x = X + (size_t)m * DD;
    float* y = Y + (size_t)m * DD;
    __shared__ float red[32];
    __shared__ float s_mu, s_rstd;

    float s = 0.f;
    for (int d = threadIdx.x; d < DD; d += 256) s += x[d];
    for (int o = 16; o; o >>= 1) s += __shfl_down_sync(0xffffffffu, s, o);
    int w = threadIdx.x >> 5, lane = threadIdx.x & 31;
    if (lane == 0) red[w] = s;
    __syncthreads();
    if (threadIdx.x == 0) {
        float t = 0.f;
        for (int i = 0; i < 8; i++) t += red[i];
        s_mu = t / (float)DD;
    }
    __syncthreads();
    float mu = s_mu;

    float s2 = 0.f;
    for (int d = threadIdx.x; d < DD; d += 256) {
        float v = x[d] - mu; s2 += v * v;
    }
    for (int o = 16; o; o >>= 1) s2 += __shfl_down_sync(0xffffffffu, s2, o);
    if (lane == 0) red[w] = s2;
    __syncthreads();
    if (threadIdx.x == 0) {
        float t = 0.f;
        for (int i = 0; i < 8; i++) t += red[i];
        s_rstd = rsqrtf(t / (float)DD + 1e-5f);
    }
    __syncthreads();
    float rstd = s_rstd;

    for (int d = threadIdx.x; d < DD; d += 256)
        y[d] = (x[d] - mu) * rstd * gam[d] + bet[d];
}

// ---------------------------------------------------------------------------
// Gate head with fused exact GELU: logits = gelu(hraw) @ W2 + b2, Gumbel y.
// ---------------------------------------------------------------------------
__global__ void k_gate(const float* __restrict__ H, const float* __restrict__ W2,
                       const float* __restrict__ b2, const float* __restrict__ gu,
                       float* __restrict__ out_gate, float* __restrict__ y) {
    int m = blockIdx.x;
    const float* h = H + (size_t)m * DD;
    float a0 = 0.f, a1 = 0.f;
    for (int k = threadIdx.x; k < DD; k += 128) {
        float hr = h[k];
        float hv = 0.5f * hr * (1.f + erff(hr * 0.70710678118654752440f));
        a0 += hv * W2[2 * k + 0];
        a1 += hv * W2[2 * k + 1];
    }
    for (int o = 16; o; o >>= 1) {
        a0 += __shfl_down_sync(0xffffffffu, a0, o);
        a1 += __shfl_down_sync(0xffffffffu, a1, o);
    }
    __shared__ float r0[4], r1[4];
    int w = threadIdx.x >> 5, lane = threadIdx.x & 31;
    if (lane == 0) { r0[w] = a0; r1[w] = a1; }
    __syncthreads();
    if (threadIdx.x == 0) {
        float l0 = r0[0] + r0[1] + r0[2] + r0[3] + b2[0];
        float l1 = r1[0] + r1[1] + r1[2] + r1[3] + b2[1];
        out_gate[2 * m + 0] = l0;
        out_gate[2 * m + 1] = l1;
        float u0 = gu[2 * m + 0], u1 = gu[2 * m + 1];
        float g0 = -logf(-logf(u0 + 1e-20f) + 1e-20f);
        float g1 = -logf(-logf(u1 + 1e-20f) + 1e-20f);
        float s0 = (l0 + 0.1f * g0) * 2.0f;   // /TEMP, TEMP=0.5
        float s1 = (l1 + 0.1f * g1) * 2.0f;
        y[m] = 1.0f / (1.0f + expf(s0 - s1)); // softmax[:,1]
    }
}

// ---------------------------------------------------------------------------
// Top-8 of 127 (stable) + z_hard output + selected frame list
// ---------------------------------------------------------------------------
__global__ void k_topk(const float* __restrict__ y, float* __restrict__ out_z) {
    if (threadIdx.x != 0 || blockIdx.x != 0) return;
    float v[NM1];
    bool taken[NM1];
    for (int i = 0; i < NM1; i++) { v[i] = y[i]; taken[i] = false; }
    out_z[0] = 1.f;
    for (int i = 0; i < NM1; i++) out_z[i + 1] = 0.f;
    g_sel[0] = 0;
    for (int r = 0; r < NC; r++) {
        float best = -1e30f; int bi = 0;
        for (int i = 0; i < NM1; i++)
            if (!taken[i] && v[i] > best) { best = v[i]; bi = i; }
        taken[bi] = true;
        g_sel[r + 1] = bi + 1;
        out_z[bi + 1] = 1.f;
    }
}

// ---------------------------------------------------------------------------
// Pooled thumbnail features from the 9 selected frames only.
// ---------------------------------------------------------------------------
__global__ void k_pool(const float* __restrict__ v, float* __restrict__ pooled) {
    int b = blockIdx.x;
    int q = b / 3, c = b % 3;
    int d = c * 512 + threadIdx.x * 4;
    float ax = 0.f, ay = 0.f, az = 0.f, aw = 0.f;
    for (int s = 0; s <= NC; s++) {
        int f = g_sel[s];
        const float* base = v + ((size_t)f * PP + q * 9) * DD + d;
#pragma unroll
        for (int p = 0; p < 9; p++) {
            float4 x = *reinterpret_cast<const float4*>(base + (size_t)p * DD);
            ax += x.x; ay += x.y; az += x.z; aw += x.w;
        }
    }
    const float inv = 1.0f / 81.0f;   // / zsum(=9) / group(=9)
    float4 r = make_float4(ax * inv, ay * inv, az * inv, aw * inv);
    *reinterpret_cast<float4*>(&pooled[(size_t)q * DD + d]) = r;
}

// ---------------------------------------------------------------------------
// Launch
// ---------------------------------------------------------------------------
extern "C" void kernel_launch(void* const* d_in, const int* in_sizes, int n_in,
                              void* d_out, int out_size) {
    const float* v     = (const float*)d_in[0];
    const float* gu    = (const float*)d_in[1];
    const float* W_agg = (const float*)d_in[2];
    const float* b_agg = (const float*)d_in[3];
    const float* ln_g  = (const float*)d_in[4];
    const float* ln_b  = (const float*)d_in[5];
    const float* W1    = (const float*)d_in[6];
    const float* b1    = (const float*)d_in[7];
    const float* W2    = (const float*)d_in[8];
    const float* b2    = (const float*)d_in[9];
    const float* W_th  = (const float*)d_in[10];
    const float* b_th  = (const float*)d_in[11];

    float* out       = (float*)d_out;
    float* out_gate  = out;                       // [127,2]
    float* out_thumb = out + NM1 * 2;             // [64,4096]
    float* out_z     = out_thumb + NQk * LMq;     // [128]

    float* scr = nullptr;
    cudaGetSymbolAddress((void**)&scr, g_scratch);
    float* mp2    = scr + OFF_MP;
    float* ema    = scr + OFF_EMA;
    float* feat   = scr + OFF_FEAT;
    float* xn     = scr + OFF_XN;
    float* h      = scr + OFF_H;
    float* pooled = scr + OFF_POOL;
    float* yv     = scr + OFF_Y;

    // Patch sums (split halves) + EMA scan
    k_mp<<<NF * 3 * 2, 128>>>(v, mp2);
    k_ema<<<DD / 128, 128>>>(mp2, ema);

    // feat = ema @ W_agg + b_agg   [127,1536]x[1536,1536]
    k_init_bias<<<(NM1 * DD + 255) / 256, 256>>>(feat, b_agg, NM1 * DD, DD);
    {
        dim3 grid(DD / 64, 2, 6);
        k_gemm_f2<<<grid, 128>>>(ema, W_agg, feat, NM1, DD, DD, DD / 6);
    }

    // LayerNorm
    k_ln<<<NM1, 256>>>(feat, xn, ln_g, ln_b);

    // h_raw = xn @ W1 + b1   (GELU fused into k_gate)
    k_init_bias<<<(NM1 * DD + 255) / 256, 256>>>(h, b1, NM1 * DD, DD);
    {
        dim3 grid(DD / 64, 2, 6);
        k_gemm_f2<<<grid, 128>>>(xn, W1, h, NM1, DD, DD, DD / 6);
    }

    // gate logits (to output) + gumbel-softmax y
    k_gate<<<NM1, 128>>>(h, W2, b2, gu, out_gate, yv);

    // top-8 + z_hard output + selected frames
    k_topk<<<1, 32>>>(yv, out_z);

    // pooled features from 9 selected frames
    k_pool<<<NQk * 3, 128>>>(v, pooled);

    // thumbnail = pooled @ W_th + b_th   [64,1536]x[1536,4096]
    k_init_bias<<<(NQk * LMq + 255) / 256, 256>>>(out_thumb, b_th, NQk * LMq, LMq);
    {
        dim3 grid(LMq / 64, 1, 3);
        k_gemm_f2<<<grid, 128>>>(pooled, W_th, out_thumb, NQk, LMq, DD, DD / 3);
    }
}

// round 4
// speedup vs baseline: 1.2918x; 1.2918x over previous
#include <cuda_runtime.h>
#include <math.h>

// Problem constants
#define NF   128
#define PP   576
#define DD   1536
#define LMq  4096
#define NQk  64
#define NM1  127
#define NC   8
#define SPLIT 4
#define PPC  (PP/SPLIT)      // 144 patches per k_mp block

// Scratch layout (no allocations allowed)
#define OFF_MP    0                            // [SPLIT][NF][DD] patch-sum parts
#define OFF_EMA   (SPLIT*NF*DD)
#define OFF_FEAT  (OFF_EMA  + NM1*DD)
#define OFF_XN    (OFF_FEAT + NM1*DD)
#define OFF_H     (OFF_XN   + NM1*DD)
#define OFF_POOL  (OFF_H    + NM1*DD)
#define OFF_Y     (OFF_POOL + NQk*DD)
#define SCRATCH_TOTAL (OFF_Y + 256)

__device__ float g_scratch[SCRATCH_TOTAL];
__device__ int   g_sel[NC + 1];

// ---------------------------------------------------------------------------
// Patch partial sums: grid = NF*3*SPLIT, 128 threads, 512 d per block.
// ---------------------------------------------------------------------------
__global__ void k_mp(const float* __restrict__ v, float* __restrict__ mp2) {
    int b = blockIdx.x;
    int hh = b & (SPLIT - 1);
    int nc = b >> 2;
    int n = nc / 3, c = nc % 3;
    int d = c * 512 + threadIdx.x * 4;
    const float* base = v + (size_t)n * PP * DD + (size_t)hh * PPC * DD + d;
    float ax = 0.f, ay = 0.f, az = 0.f, aw = 0.f;
#pragma unroll 8
    for (int p = 0; p < PPC; p++) {
        float4 x = *reinterpret_cast<const float4*>(base + (size_t)p * DD);
        ax += x.x; ay += x.y; az += x.z; aw += x.w;
    }
    float4 r = make_float4(ax, ay, az, aw);
    *reinterpret_cast<float4*>(&mp2[(size_t)hh * NF * DD + (size_t)n * DD + d]) = r;
}

// ---------------------------------------------------------------------------
// Chunked-parallel momentum EMA. 8 chunks of 16 outputs, warm-up window
// clamped to 0 (carry error <= 0.5^26 ~ 1.5e-8 for chunks that truncate).
// grid = (DD/256)*8 = 48 blocks, 256 threads.
// ---------------------------------------------------------------------------
__device__ __forceinline__ float mp_mean(const float* mp2, int i, int d) {
    const float inv = 1.0f / (float)PP;
    float s = mp2[(size_t)i * DD + d];
#pragma unroll
    for (int h = 1; h < SPLIT; h++) s += mp2[(size_t)(h * NF + i) * DD + d];
    return s * inv;
}
__global__ void k_ema(const float* __restrict__ mp2, float* __restrict__ ema) {
    int bx = blockIdx.x;
    int d = (bx >> 3) * 256 + threadIdx.x;
    int c = bx & 7;
    int s = c * 16;
    int w = s - 26; if (w < 0) w = 0;          // FIX: clamp warm-up start
    int e_end = min(s + 16, NM1);
    float prev = mp_mean(mp2, w, d);
    float e = 0.f;
    for (int i = w; i < e_end; i++) {
        float cur = mp_mean(mp2, i + 1, d);
        float diff = cur - prev;
        e = (i == w) ? diff : (0.5f * diff + 0.5f * e);
        if (i >= s) ema[(size_t)i * DD + d] = e;
        prev = cur;
    }
}

// ---------------------------------------------------------------------------
// Bias init
// ---------------------------------------------------------------------------
__global__ void k_init_bias(float* __restrict__ C, const float* __restrict__ bias,
                            int total, int Nn) {
    int idx = blockIdx.x * blockDim.x + threadIdx.x;
    if (idx < total) C[idx] = bias[idx % Nn];
}

// ---------------------------------------------------------------------------
// Classic register-blocked SGEMM, split-K, atomic epilogue.
// Block tile BM x 128, BK=16, 256 threads (16x16), micro (BM/16) x 8.
// Global->reg prefetch pipeline across k-tiles. C += A[M,K]@B[K,N].
// ---------------------------------------------------------------------------
template <int BM>
__global__ __launch_bounds__(256, 1)
void k_gemm(const float* __restrict__ A, const float* __restrict__ B,
            float* __restrict__ C, int M, int Nn, int K, int Kc) {
    constexpr int MR = BM / 16;             // 8 or 4
    constexpr int AG = BM / 64;             // float4 granules per thread for A
    __shared__ __align__(16) float As[16][BM + 4];
    __shared__ __align__(16) float Bs[16][132];

    const int n0 = blockIdx.x * 128;
    const int m0 = blockIdx.y * BM;
    const int k0 = blockIdx.z * Kc;
    const int tid = threadIdx.x;
    const int tx = tid & 15, ty = tid >> 4;

    float acc[MR][8];
#pragma unroll
    for (int i = 0; i < MR; i++)
#pragma unroll
        for (int j = 0; j < 8; j++) acc[i][j] = 0.f;

    float4 aR[AG], bR[2];

    auto loadG = [&](int kb) {
#pragma unroll
        for (int i = 0; i < AG; i++) {
            int g = tid + i * 256;
            int m = g >> 2, k4 = (g & 3) << 2;
            int mm = m0 + m;
            aR[i] = (mm < M) ? *reinterpret_cast<const float4*>(A + (size_t)mm * K + kb + k4)
                             : make_float4(0.f, 0.f, 0.f, 0.f);
        }
#pragma unroll
        for (int i = 0; i < 2; i++) {
            int g = tid + i * 256;
            int k = g >> 5, n4 = (g & 31) << 2;
            bR[i] = *reinterpret_cast<const float4*>(B + (size_t)(kb + k) * Nn + n0 + n4);
        }
    };
    auto storeS = [&]() {
#pragma unroll
        for (int i = 0; i < AG; i++) {
            int g = tid + i * 256;
            int m = g >> 2, k4 = (g & 3) << 2;
            As[k4 + 0][m] = aR[i].x; As[k4 + 1][m] = aR[i].y;
            As[k4 + 2][m] = aR[i].z; As[k4 + 3][m] = aR[i].w;
        }
#pragma unroll
        for (int i = 0; i < 2; i++) {
            int g = tid + i * 256;
            int k = g >> 5, n4 = (g & 31) << 2;
            *reinterpret_cast<float4*>(&Bs[k][n4]) = bR[i];
        }
    };
    auto compute = [&]() {
#pragma unroll
        for (int kk = 0; kk < 16; kk++) {
            float af[MR], bf[8];
#pragma unroll
            for (int i = 0; i < MR; i += 4) {
                float4 a = *reinterpret_cast<const float4*>(&As[kk][ty * MR + i]);
                af[i] = a.x; af[i + 1] = a.y; af[i + 2] = a.z; af[i + 3] = a.w;
            }
#pragma unroll
            for (int j = 0; j < 8; j += 4) {
                float4 b = *reinterpret_cast<const float4*>(&Bs[kk][tx * 8 + j]);
                bf[j] = b.x; bf[j + 1] = b.y; bf[j + 2] = b.z; bf[j + 3] = b.w;
            }
#pragma unroll
            for (int i = 0; i < MR; i++)
#pragma unroll
                for (int j = 0; j < 8; j++) acc[i][j] += af[i] * bf[j];
        }
    };

    loadG(k0);
    storeS();
    __syncthreads();
    for (int kb = k0 + 16; kb < k0 + Kc; kb += 16) {
        loadG(kb);
        compute();
        __syncthreads();
        storeS();
        __syncthreads();
    }
    compute();

#pragma unroll
    for (int i = 0; i < MR; i++) {
        int m = m0 + ty * MR + i;
        if (m < M) {
            float* crow = C + (size_t)m * Nn + n0 + tx * 8;
#pragma unroll
            for (int j = 0; j < 8; j++) atomicAdd(&crow[j], acc[i][j]);
        }
    }
}

// ---------------------------------------------------------------------------
// LayerNorm per row (two-pass)
// ---------------------------------------------------------------------------
__global__ void k_ln(const float* __restrict__ X, float* __restrict__ Y,
                     const float* __restrict__ gam, const float* __restrict__ bet) {
    int m = blockIdx.x;
    const float* x = X + (size_t)m * DD;
    float* y = Y + (size_t)m * DD;
    __shared__ float red[32];
    __shared__ float s_mu, s_rstd;

    float s = 0.f;
    for (int d = threadIdx.x; d < DD; d += 256) s += x[d];
    for (int o = 16; o; o >>= 1) s += __shfl_down_sync(0xffffffffu, s, o);
    int w = threadIdx.x >> 5, lane = threadIdx.x & 31;
    if (lane == 0) red[w] = s;
    __syncthreads();
    if (threadIdx.x == 0) {
        float t = 0.f;
        for (int i = 0; i < 8; i++) t += red[i];
        s_mu = t / (float)DD;
    }
    __syncthreads();
    float mu = s_mu;

    float s2 = 0.f;
    for (int d = threadIdx.x; d < DD; d += 256) {
        float v = x[d] - mu; s2 += v * v;
    }
    for (int o = 16; o; o >>= 1) s2 += __shfl_down_sync(0xffffffffu, s2, o);
    if (lane == 0) red[w] = s2;
    __syncthreads();
    if (threadIdx.x == 0) {
        float t = 0.f;
        for (int i = 0; i < 8; i++) t += red[i];
        s_rstd = rsqrtf(t / (float)DD + 1e-5f);
    }
    __syncthreads();
    float rstd = s_rstd;

    for (int d = threadIdx.x; d < DD; d += 256)
        y[d] = (x[d] - mu) * rstd * gam[d] + bet[d];
}

// ---------------------------------------------------------------------------
// Gate head with fused exact GELU + Gumbel softmax y
// ---------------------------------------------------------------------------
__global__ void k_gate(const float* __restrict__ H, const float* __restrict__ W2,
                       const float* __restrict__ b2, const float* __restrict__ gu,
                       float* __restrict__ out_gate, float* __restrict__ y) {
    int m = blockIdx.x;
    const float* h = H + (size_t)m * DD;
    float a0 = 0.f, a1 = 0.f;
    for (int k = threadIdx.x; k < DD; k += 128) {
        float hr = h[k];
        float hv = 0.5f * hr * (1.f + erff(hr * 0.70710678118654752440f));
        a0 += hv * W2[2 * k + 0];
        a1 += hv * W2[2 * k + 1];
    }
    for (int o = 16; o; o >>= 1) {
        a0 += __shfl_down_sync(0xffffffffu, a0, o);
        a1 += __shfl_down_sync(0xffffffffu, a1, o);
    }
    __shared__ float r0[4], r1[4];
    int w = threadIdx.x >> 5, lane = threadIdx.x & 31;
    if (lane == 0) { r0[w] = a0; r1[w] = a1; }
    __syncthreads();
    if (threadIdx.x == 0) {
        float l0 = r0[0] + r0[1] + r0[2] + r0[3] + b2[0];
        float l1 = r1[0] + r1[1] + r1[2] + r1[3] + b2[1];
        out_gate[2 * m + 0] = l0;
        out_gate[2 * m + 1] = l1;
        float u0 = gu[2 * m + 0], u1 = gu[2 * m + 1];
        float g0 = -logf(-logf(u0 + 1e-20f) + 1e-20f);
        float g1 = -logf(-logf(u1 + 1e-20f) + 1e-20f);
        float s0 = (l0 + 0.1f * g0) * 2.0f;   // /TEMP, TEMP=0.5
        float s1 = (l1 + 0.1f * g1) * 2.0f;
        y[m] = 1.0f / (1.0f + expf(s0 - s1)); // softmax[:,1]
    }
}

// ---------------------------------------------------------------------------
// Parallel top-8 of 127 (lowest index wins ties) + z_hard + selection list
// ---------------------------------------------------------------------------
__global__ void k_topk(const float* __restrict__ y, float* __restrict__ out_z) {
    __shared__ float sv[128];
    __shared__ int   si[128];
    int tid = threadIdx.x;
    float val = (tid < NM1) ? y[tid] : -1e30f;
    if (tid == 0) { out_z[0] = 1.f; g_sel[0] = 0; }
    if (tid < NM1) out_z[tid + 1] = 0.f;
    __syncthreads();
    for (int r = 0; r < NC; r++) {
        sv[tid] = val; si[tid] = tid;
        __syncthreads();
        for (int o = 64; o; o >>= 1) {
            if (tid < o) {
                float ov = sv[tid + o]; int oi = si[tid + o];
                if (ov > sv[tid] || (ov == sv[tid] && oi < si[tid])) {
                    sv[tid] = ov; si[tid] = oi;
                }
            }
            __syncthreads();
        }
        int wn = si[0];
        if (tid == wn) val = -1e30f;
        if (tid == 0) { g_sel[r + 1] = wn + 1; out_z[wn + 1] = 1.f; }
        __syncthreads();
    }
}

// ---------------------------------------------------------------------------
// Pooled thumbnail features from the 9 selected frames
// ---------------------------------------------------------------------------
__global__ void k_pool(const float* __restrict__ v, float* __restrict__ pooled) {
    int b = blockIdx.x;
    int q = b / 3, c = b % 3;
    int d = c * 512 + threadIdx.x * 4;
    float ax = 0.f, ay = 0.f, az = 0.f, aw = 0.f;
    for (int s = 0; s <= NC; s++) {
        int f = g_sel[s];
        const float* base = v + ((size_t)f * PP + q * 9) * DD + d;
#pragma unroll
        for (int p = 0; p < 9; p++) {
            float4 x = *reinterpret_cast<const float4*>(base + (size_t)p * DD);
            ax += x.x; ay += x.y; az += x.z; aw += x.w;
        }
    }
    const float inv = 1.0f / 81.0f;   // / zsum(=9) / group(=9)
    float4 r = make_float4(ax * inv, ay * inv, az * inv, aw * inv);
    *reinterpret_cast<float4*>(&pooled[(size_t)q * DD + d]) = r;
}

// ---------------------------------------------------------------------------
// Launch
// ---------------------------------------------------------------------------
extern "C" void kernel_launch(void* const* d_in, const int* in_sizes, int n_in,
                              void* d_out, int out_size) {
    const float* v     = (const float*)d_in[0];
    const float* gu    = (const float*)d_in[1];
    const float* W_agg = (const float*)d_in[2];
    const float* b_agg = (const float*)d_in[3];
    const float* ln_g  = (const float*)d_in[4];
    const float* ln_b  = (const float*)d_in[5];
    const float* W1    = (const float*)d_in[6];
    const float* b1    = (const float*)d_in[7];
    const float* W2    = (const float*)d_in[8];
    const float* b2    = (const float*)d_in[9];
    const float* W_th  = (const float*)d_in[10];
    const float* b_th  = (const float*)d_in[11];

    float* out       = (float*)d_out;
    float* out_gate  = out;                       // [127,2]
    float* out_thumb = out + NM1 * 2;             // [64,4096]
    float* out_z     = out_thumb + NQk * LMq;     // [128]

    float* scr = nullptr;
    cudaGetSymbolAddress((void**)&scr, g_scratch);
    float* mp2    = scr + OFF_MP;
    float* ema    = scr + OFF_EMA;
    float* feat   = scr + OFF_FEAT;
    float* xn     = scr + OFF_XN;
    float* h      = scr + OFF_H;
    float* pooled = scr + OFF_POOL;
    float* yv     = scr + OFF_Y;

    // Patch partial sums + chunked EMA scan
    k_mp<<<NF * 3 * SPLIT, 128>>>(v, mp2);
    k_ema<<<(DD / 256) * 8, 256>>>(mp2, ema);

    // feat = ema @ W_agg + b_agg   [127,1536]x[1536,1536]
    k_init_bias<<<(NM1 * DD + 255) / 256, 256>>>(feat, b_agg, NM1 * DD, DD);
    {
        dim3 grid(DD / 128, 1, 12);
        k_gemm<128><<<grid, 256>>>(ema, W_agg, feat, NM1, DD, DD, DD / 12);
    }

    // LayerNorm
    k_ln<<<NM1, 256>>>(feat, xn, ln_g, ln_b);

    // h_raw = xn @ W1 + b1  (GELU fused into k_gate)
    k_init_bias<<<(NM1 * DD + 255) / 256, 256>>>(h, b1, NM1 * DD, DD);
    {
        dim3 grid(DD / 128, 1, 12);
        k_gemm<128><<<grid, 256>>>(xn, W1, h, NM1, DD, DD, DD / 12);
    }

    // gate logits + gumbel-softmax y
    k_gate<<<NM1, 128>>>(h, W2, b2, gu, out_gate, yv);

    // top-8 + z_hard + selected frames
    k_topk<<<1, 128>>>(yv, out_z);

    // pooled features from 9 selected frames
    k_pool<<<NQk * 3, 128>>>(v, pooled);

    // thumbnail = pooled @ W_th + b_th   [64,1536]x[1536,4096]
    k_init_bias<<<(NQk * LMq + 255) / 256, 256>>>(out_thumb, b_th, NQk * LMq, LMq);
    {
        dim3 grid(LMq / 128, 1, 6);
        k_gemm<64><<<grid, 256>>>(pooled, W_th, out_thumb, NQk, LMq, DD, DD / 6);
    }
}

// round 6
// speedup vs baseline: 1.3899x; 1.0760x over previous
#include <cuda_runtime.h>
#include <cuda_bf16.h>
#include <math.h>
#include <cstdint>

// Problem constants
#define NF   128
#define PP   576
#define DD   1536
#define LMq  4096
#define NQk  64
#define NM1  127
#define NC   8
#define SPLIT 4
#define PPC  (PP/SPLIT)

// Float scratch
#define OFF_MP    0
#define OFF_EMA   (SPLIT*NF*DD)
#define OFF_FEAT  (OFF_EMA  + NM1*DD)
#define OFF_XN    (OFF_FEAT + NM1*DD)
#define OFF_H     (OFF_XN   + NM1*DD)
#define OFF_POOL  (OFF_H    + NM1*DD)
#define OFF_Y     (OFF_POOL + NQk*DD)
#define SCRATCH_TOTAL (OFF_Y + 256)

__device__ float g_scratch[SCRATCH_TOTAL];
__device__ int   g_sel[NC + 1];

// bf16 split operands (hi + lo residual), K-major rows
__device__ __nv_bfloat16 g_hiA[128 * DD];
__device__ __nv_bfloat16 g_loA[128 * DD];
__device__ __nv_bfloat16 g_hiB[LMq * DD];
__device__ __nv_bfloat16 g_loB[LMq * DD];

// ---------------------------------------------------------------------------
// Patch partial sums
// ---------------------------------------------------------------------------
__global__ void k_mp(const float* __restrict__ v, float* __restrict__ mp2) {
    int b = blockIdx.x;
    int hh = b & (SPLIT - 1);
    int nc = b >> 2;
    int n = nc / 3, c = nc % 3;
    int d = c * 512 + threadIdx.x * 4;
    const float* base = v + (size_t)n * PP * DD + (size_t)hh * PPC * DD + d;
    float ax = 0.f, ay = 0.f, az = 0.f, aw = 0.f;
#pragma unroll 8
    for (int p = 0; p < PPC; p++) {
        float4 x = *reinterpret_cast<const float4*>(base + (size_t)p * DD);
        ax += x.x; ay += x.y; az += x.z; aw += x.w;
    }
    float4 r = make_float4(ax, ay, az, aw);
    *reinterpret_cast<float4*>(&mp2[(size_t)hh * NF * DD + (size_t)n * DD + d]) = r;
}

// ---------------------------------------------------------------------------
// Chunked-parallel momentum EMA (warm-up clamped at 0)
// ---------------------------------------------------------------------------
__device__ __forceinline__ float mp_mean(const float* mp2, int i, int d) {
    const float inv = 1.0f / (float)PP;
    float s = mp2[(size_t)i * DD + d];
#pragma unroll
    for (int h = 1; h < SPLIT; h++) s += mp2[(size_t)(h * NF + i) * DD + d];
    return s * inv;
}
__global__ void k_ema(const float* __restrict__ mp2, float* __restrict__ ema) {
    int bx = blockIdx.x;
    int d = (bx >> 3) * 256 + threadIdx.x;
    int c = bx & 7;
    int s = c * 16;
    int w = s - 26; if (w < 0) w = 0;
    int e_end = min(s + 16, NM1);
    float prev = mp_mean(mp2, w, d);
    float e = 0.f;
    for (int i = w; i < e_end; i++) {
        float cur = mp_mean(mp2, i + 1, d);
        float diff = cur - prev;
        e = (i == w) ? diff : (0.5f * diff + 0.5f * e);
        if (i >= s) ema[(size_t)i * DD + d] = e;
        prev = cur;
    }
}

// ---------------------------------------------------------------------------
// Bias init
// ---------------------------------------------------------------------------
__global__ void k_init_bias(float* __restrict__ C, const float* __restrict__ bias,
                            int total, int Nn) {
    int idx = blockIdx.x * blockDim.x + threadIdx.x;
    if (idx < total) C[idx] = bias[idx % Nn];
}

// ---------------------------------------------------------------------------
// Convert A [M,1536] fp32 -> hi/lo bf16, zero-padded to 128 rows.
// ---------------------------------------------------------------------------
__global__ void k_cvtA(const float* __restrict__ A, int M,
                       __nv_bfloat16* __restrict__ hi, __nv_bfloat16* __restrict__ lo) {
    int idx = blockIdx.x * 256 + threadIdx.x;
    int m = idx / DD;
    float a = (m < M) ? A[idx] : 0.f;
    __nv_bfloat16 h = __float2bfloat16(a);
    hi[idx] = h;
    lo[idx] = __float2bfloat16(a - __bfloat162float(h));
}

// ---------------------------------------------------------------------------
// Convert+transpose B [1536,N] fp32 -> hi/lo bf16 [N,1536] (K-major rows).
// block (32,8), grid (N/32, 1536/32)
// ---------------------------------------------------------------------------
__global__ void k_cvtB(const float* __restrict__ B, int N,
                       __nv_bfloat16* __restrict__ hi, __nv_bfloat16* __restrict__ lo) {
    __shared__ float t[32][33];
    int n0 = blockIdx.x * 32, k0 = blockIdx.y * 32;
    int tx = threadIdx.x, ty = threadIdx.y;
#pragma unroll
    for (int i = 0; i < 32; i += 8)
        t[ty + i][tx] = B[(size_t)(k0 + ty + i) * N + n0 + tx];
    __syncthreads();
#pragma unroll
    for (int i = 0; i < 32; i += 8) {
        float v = t[tx][ty + i];
        size_t o = (size_t)(n0 + ty + i) * DD + k0 + tx;
        __nv_bfloat16 h = __float2bfloat16(v);
        hi[o] = h;
        lo[o] = __float2bfloat16(v - __bfloat162float(h));
    }
}

// ---------------------------------------------------------------------------
// bf16 mma.sync GEMM, 3-term split accumulated in registers:
//   C += hiA@hiB^T + loA@hiB^T + hiA@loB^T
// CTA: 256 thr = 8 warps (4M x 2N). Tile M=128 x N=64, BK=64.
// grid(Ntot/64, 1, S) split-K, Kcta multiple of 64. Atomic epilogue.
// ---------------------------------------------------------------------------
#define ASTR 72
__global__ __launch_bounds__(256, 1)
void k_gemm_mma(const __nv_bfloat16* __restrict__ hiA, const __nv_bfloat16* __restrict__ loA,
                const __nv_bfloat16* __restrict__ hiB, const __nv_bfloat16* __restrict__ loB,
                float* __restrict__ C, int M, int Ntot, int Kcta) {
    __shared__ __align__(16) __nv_bfloat16 As[128 * ASTR];
    __shared__ __align__(16) __nv_bfloat16 Bs[64 * ASTR];

    const int tid = threadIdx.x;
    const int lane = tid & 31, wid = tid >> 5;
    const int wm = wid & 3, wn = wid >> 2;        // warp tile: 32M x 32N
    const int gid = lane >> 2, qd = lane & 3;
    const int n0 = blockIdx.x * 64;
    const int kb = blockIdx.z * Kcta;

    float acc[2][4][4];
#pragma unroll
    for (int i = 0; i < 2; i++)
#pragma unroll
        for (int j = 0; j < 4; j++)
#pragma unroll
            for (int q = 0; q < 4; q++) acc[i][j][q] = 0.f;

    for (int pass = 0; pass < 3; pass++) {
        const __nv_bfloat16* Asrc = (pass == 1) ? loA : hiA;
        const __nv_bfloat16* Bsrc = (pass == 2) ? loB : hiB;

        for (int kc = kb; kc < kb + Kcta; kc += 64) {
            // Load A [128 x 64], B [64 x 64] bf16 tiles (uint4 = 8 bf16)
#pragma unroll
            for (int it = 0; it < 4; it++) {
                int g = tid + it * 256;            // 0..1023
                int r = g >> 3, q = g & 7;
                *reinterpret_cast<uint4*>(&As[r * ASTR + q * 8]) =
                    *reinterpret_cast<const uint4*>(Asrc + (size_t)r * DD + kc + q * 8);
            }
#pragma unroll
            for (int it = 0; it < 2; it++) {
                int g = tid + it * 256;            // 0..511
                int r = g >> 3, q = g & 7;
                *reinterpret_cast<uint4*>(&Bs[r * ASTR + q * 8]) =
                    *reinterpret_cast<const uint4*>(Bsrc + (size_t)(n0 + r) * DD + kc + q * 8);
            }
            __syncthreads();

#pragma unroll
            for (int ks = 0; ks < 4; ks++) {
                uint32_t a[2][4];
#pragma unroll
                for (int mt = 0; mt < 2; mt++) {
                    int r0 = wm * 32 + mt * 16 + gid;
                    int cb = ks * 16 + qd * 2;
                    a[mt][0] = *reinterpret_cast<const uint32_t*>(&As[r0 * ASTR + cb]);
                    a[mt][1] = *reinterpret_cast<const uint32_t*>(&As[(r0 + 8) * ASTR + cb]);
                    a[mt][2] = *reinterpret_cast<const uint32_t*>(&As[r0 * ASTR + cb + 8]);
                    a[mt][3] = *reinterpret_cast<const uint32_t*>(&As[(r0 + 8) * ASTR + cb + 8]);
                }
                uint32_t bfr[4][2];
#pragma unroll
                for (int nt = 0; nt < 4; nt++) {
                    int nn = wn * 32 + nt * 8 + gid;
                    int cb = ks * 16 + qd * 2;
                    bfr[nt][0] = *reinterpret_cast<const uint32_t*>(&Bs[nn * ASTR + cb]);
                    bfr[nt][1] = *reinterpret_cast<const uint32_t*>(&Bs[nn * ASTR + cb + 8]);
                }
#pragma unroll
                for (int mt = 0; mt < 2; mt++)
#pragma unroll
                    for (int nt = 0; nt < 4; nt++) {
                        asm volatile(
                            "mma.sync.aligned.m16n8k16.row.col.f32.bf16.bf16.f32 "
                            "{%0,%1,%2,%3}, {%4,%5,%6,%7}, {%8,%9}, {%0,%1,%2,%3};"
                            : "+f"(acc[mt][nt][0]), "+f"(acc[mt][nt][1]),
                              "+f"(acc[mt][nt][2]), "+f"(acc[mt][nt][3])
                            : "r"(a[mt][0]), "r"(a[mt][1]), "r"(a[mt][2]), "r"(a[mt][3]),
                              "r"(bfr[nt][0]), "r"(bfr[nt][1]));
                    }
            }
            __syncthreads();
        }
    }

    // Atomic epilogue (split-K partial sums)
#pragma unroll
    for (int mt = 0; mt < 2; mt++) {
        int r0 = wm * 32 + mt * 16 + gid;
#pragma unroll
        for (int nt = 0; nt < 4; nt++) {
            int cc = n0 + wn * 32 + nt * 8 + qd * 2;
            if (r0 < M) {
                atomicAdd(&C[(size_t)r0 * Ntot + cc],     acc[mt][nt][0]);
                atomicAdd(&C[(size_t)r0 * Ntot + cc + 1], acc[mt][nt][1]);
            }
            if (r0 + 8 < M) {
                atomicAdd(&C[(size_t)(r0 + 8) * Ntot + cc],     acc[mt][nt][2]);
                atomicAdd(&C[(size_t)(r0 + 8) * Ntot + cc + 1], acc[mt][nt][3]);
            }
        }
    }
}

// ---------------------------------------------------------------------------
// LayerNorm per row
// ---------------------------------------------------------------------------
__global__ void k_ln(const float* __restrict__ X, float* __restrict__ Y,
                     const float* __restrict__ gam, const float* __restrict__ bet) {
    int m = blockIdx.x;
    const float* x = X + (size_t)m * DD;
    float* y = Y + (size_t)m * DD;
    __shared__ float red[32];
    __shared__ float s_mu, s_rstd;

    float s = 0.f;
    for (int d = threadIdx.x; d < DD; d += 256) s += x[d];
    for (int o = 16; o; o >>= 1) s += __shfl_down_sync(0xffffffffu, s, o);
    int w = threadIdx.x >> 5, lane = threadIdx.x & 31;
    if (lane == 0) red[w] = s;
    __syncthreads();
    if (threadIdx.x == 0) {
        float t = 0.f;
        for (int i = 0; i < 8; i++) t += red[i];
        s_mu = t / (float)DD;
    }
    __syncthreads();
    float mu = s_mu;

    float s2 = 0.f;
    for (int d = threadIdx.x; d < DD; d += 256) {
        float v = x[d] - mu; s2 += v * v;
    }
    for (int o = 16; o; o >>= 1) s2 += __shfl_down_sync(0xffffffffu, s2, o);
    if (lane == 0) red[w] = s2;
    __syncthreads();
    if (threadIdx.x == 0) {
        float t = 0.f;
        for (int i = 0; i < 8; i++) t += red[i];
        s_rstd = rsqrtf(t / (float)DD + 1e-5f);
    }
    __syncthreads();
    float rstd = s_rstd;

    for (int d = threadIdx.x; d < DD; d += 256)
        y[d] = (x[d] - mu) * rstd * gam[d] + bet[d];
}

// ---------------------------------------------------------------------------
// Gate head with fused exact GELU + Gumbel softmax y
// ---------------------------------------------------------------------------
__global__ void k_gate(const float* __restrict__ H, const float* __restrict__ W2,
                       const float* __restrict__ b2, const float* __restrict__ gu,
                       float* __restrict__ out_gate, float* __restrict__ y) {
    int m = blockIdx.x;
    const float* h = H + (size_t)m * DD;
    float a0 = 0.f, a1 = 0.f;
    for (int k = threadIdx.x; k < DD; k += 128) {
        float hr = h[k];
        float hv = 0.5f * hr * (1.f + erff(hr * 0.70710678118654752440f));
        a0 += hv * W2[2 * k + 0];
        a1 += hv * W2[2 * k + 1];
    }
    for (int o = 16; o; o >>= 1) {
        a0 += __shfl_down_sync(0xffffffffu, a0, o);
        a1 += __shfl_down_sync(0xffffffffu, a1, o);
    }
    __shared__ float r0[4], r1[4];
    int w = threadIdx.x >> 5, lane = threadIdx.x & 31;
    if (lane == 0) { r0[w] = a0; r1[w] = a1; }
    __syncthreads();
    if (threadIdx.x == 0) {
        float l0 = r0[0] + r0[1] + r0[2] + r0[3] + b2[0];
        float l1 = r1[0] + r1[1] + r1[2] + r1[3] + b2[1];
        out_gate[2 * m + 0] = l0;
        out_gate[2 * m + 1] = l1;
        float u0 = gu[2 * m + 0], u1 = gu[2 * m + 1];
        float g0 = -logf(-logf(u0 + 1e-20f) + 1e-20f);
        float g1 = -logf(-logf(u1 + 1e-20f) + 1e-20f);
        float s0 = (l0 + 0.1f * g0) * 2.0f;
        float s1 = (l1 + 0.1f * g1) * 2.0f;
        y[m] = 1.0f / (1.0f + expf(s0 - s1));
    }
}

// ---------------------------------------------------------------------------
// Parallel top-8 of 127 + z_hard + selection list
// ---------------------------------------------------------------------------
__global__ void k_topk(const float* __restrict__ y, float* __restrict__ out_z) {
    __shared__ float sv[128];
    __shared__ int   si[128];
    int tid = threadIdx.x;
    float val = (tid < NM1) ? y[tid] : -1e30f;
    if (tid == 0) { out_z[0] = 1.f; g_sel[0] = 0; }
    if (tid < NM1) out_z[tid + 1] = 0.f;
    __syncthreads();
    for (int r = 0; r < NC; r++) {
        sv[tid] = val; si[tid] = tid;
        __syncthreads();
        for (int o = 64; o; o >>= 1) {
            if (tid < o) {
                float ov = sv[tid + o]; int oi = si[tid + o];
                if (ov > sv[tid] || (ov == sv[tid] && oi < si[tid])) {
                    sv[tid] = ov; si[tid] = oi;
                }
            }
            __syncthreads();
        }
        int wn = si[0];
        if (tid == wn) val = -1e30f;
        if (tid == 0) { g_sel[r + 1] = wn + 1; out_z[wn + 1] = 1.f; }
        __syncthreads();
    }
}

// ---------------------------------------------------------------------------
// Pooled thumbnail features from the 9 selected frames
// ---------------------------------------------------------------------------
__global__ void k_pool(const float* __restrict__ v, float* __restrict__ pooled) {
    int b = blockIdx.x;
    int q = b / 3, c = b % 3;
    int d = c * 512 + threadIdx.x * 4;
    float ax = 0.f, ay = 0.f, az = 0.f, aw = 0.f;
    for (int s = 0; s <= NC; s++) {
        int f = g_sel[s];
        const float* base = v + ((size_t)f * PP + q * 9) * DD + d;
#pragma unroll
        for (int p = 0; p < 9; p++) {
            float4 x = *reinterpret_cast<const float4*>(base + (size_t)p * DD);
            ax += x.x; ay += x.y; az += x.z; aw += x.w;
        }
    }
    const float inv = 1.0f / 81.0f;
    float4 r = make_float4(ax * inv, ay * inv, az * inv, aw * inv);
    *reinterpret_cast<float4*>(&pooled[(size_t)q * DD + d]) = r;
}

// ---------------------------------------------------------------------------
// Launch
// ---------------------------------------------------------------------------
extern "C" void kernel_launch(void* const* d_in, const int* in_sizes, int n_in,
                              void* d_out, int out_size) {
    const float* v     = (const float*)d_in[0];
    const float* gu    = (const float*)d_in[1];
    const float* W_agg = (const float*)d_in[2];
    const float* b_agg = (const float*)d_in[3];
    const float* ln_g  = (const float*)d_in[4];
    const float* ln_b  = (const float*)d_in[5];
    const float* W1    = (const float*)d_in[6];
    const float* b1    = (const float*)d_in[7];
    const float* W2    = (const float*)d_in[8];
    const float* b2    = (const float*)d_in[9];
    const float* W_th  = (const float*)d_in[10];
    const float* b_th  = (const float*)d_in[11];

    float* out       = (float*)d_out;
    float* out_gate  = out;
    float* out_thumb = out + NM1 * 2;
    float* out_z     = out_thumb + NQk * LMq;

    float* scr = nullptr;
    cudaGetSymbolAddress((void**)&scr, g_scratch);
    float* mp2    = scr + OFF_MP;
    float* ema    = scr + OFF_EMA;
    float* feat   = scr + OFF_FEAT;
    float* xn     = scr + OFF_XN;
    float* h      = scr + OFF_H;
    float* pooled = scr + OFF_POOL;
    float* yv     = scr + OFF_Y;

    __nv_bfloat16 *hiA, *loA, *hiB, *loB;
    cudaGetSymbolAddress((void**)&hiA, g_hiA);
    cudaGetSymbolAddress((void**)&loA, g_loA);
    cudaGetSymbolAddress((void**)&hiB, g_hiB);
    cudaGetSymbolAddress((void**)&loB, g_loB);

    // Patch sums + EMA
    k_mp<<<NF * 3 * SPLIT, 128>>>(v, mp2);
    k_ema<<<(DD / 256) * 8, 256>>>(mp2, ema);

    // GEMM1: feat = ema @ W_agg + b_agg
    k_cvtA<<<128 * DD / 256, 256>>>(ema, NM1, hiA, loA);
    {
        dim3 gb(DD / 32, DD / 32);
        k_cvtB<<<gb, dim3(32, 8)>>>(W_agg, DD, hiB, loB);
    }
    k_init_bias<<<(NM1 * DD + 255) / 256, 256>>>(feat, b_agg, NM1 * DD, DD);
    {
        dim3 grid(DD / 64, 1, 6);
        k_gemm_mma<<<grid, 256>>>(hiA, loA, hiB, loB, feat, NM1, DD, DD / 6);
    }

    // LayerNorm
    k_ln<<<NM1, 256>>>(feat, xn, ln_g, ln_b);

    // GEMM2: h = xn @ W1 + b1 (GELU fused into gate)
    k_cvtA<<<128 * DD / 256, 256>>>(xn, NM1, hiA, loA);
    {
        dim3 gb(DD / 32, DD / 32);
        k_cvtB<<<gb, dim3(32, 8)>>>(W1, DD, hiB, loB);
    }
    k_init_bias<<<(NM1 * DD + 255) / 256, 256>>>(h, b1, NM1 * DD, DD);
    {
        dim3 grid(DD / 64, 1, 6);
        k_gemm_mma<<<grid, 256>>>(hiA, loA, hiB, loB, h, NM1, DD, DD / 6);
    }

    // gate + topk + pool
    k_gate<<<NM1, 128>>>(h, W2, b2, gu, out_gate, yv);
    k_topk<<<1, 128>>>(yv, out_z);
    k_pool<<<NQk * 3, 128>>>(v, pooled);

    // GEMM3: thumbnail = pooled @ W_th + b_th
    k_cvtA<<<128 * DD / 256, 256>>>(pooled, NQk, hiA, loA);
    {
        dim3 gb(LMq / 32, DD / 32);
        k_cvtB<<<gb, dim3(32, 8)>>>(W_th, LMq, hiB, loB);
    }
    k_init_bias<<<(NQk * LMq + 255) / 256, 256>>>(out_thumb, b_th, NQk * LMq, LMq);
    {
        dim3 grid(LMq / 64, 1, 3);
        k_gemm_mma<<<grid, 256>>>(hiA, loA, hiB, loB, out_thumb, NQk, LMq, DD / 3);
    }
}

// round 7
// speedup vs baseline: 1.4992x; 1.0786x over previous
#include <cuda_runtime.h>
#include <cuda_bf16.h>
#include <math.h>
#include <cstdint>

// Problem constants
#define NF   128
#define PP   576
#define DD   1536
#define LMq  4096
#define NQk  64
#define NM1  127
#define NC   8
#define SPLIT 4
#define PPC  (PP/SPLIT)

// Float scratch
#define OFF_MP    0
#define OFF_FEAT  (SPLIT*NF*DD)
#define OFF_H     (OFF_FEAT + NM1*DD)
#define OFF_Y     (OFF_H    + NM1*DD)
#define SCRATCH_TOTAL (OFF_Y + 256)

__device__ float g_scratch[SCRATCH_TOTAL];
__device__ int   g_sel[NC + 1];

// bf16 hi/lo A operand (padded to 128 rows), written directly by producers
__device__ __nv_bfloat16 g_hiA[128 * DD];
__device__ __nv_bfloat16 g_loA[128 * DD];

__device__ __forceinline__ void split_bf16(float a, __nv_bfloat16& h, __nv_bfloat16& l) {
    h = __float2bfloat16(a);
    l = __float2bfloat16(a - __bfloat162float(h));
}

// ---------------------------------------------------------------------------
// Patch partial sums
// ---------------------------------------------------------------------------
__global__ void k_mp(const float* __restrict__ v, float* __restrict__ mp2) {
    int b = blockIdx.x;
    int hh = b & (SPLIT - 1);
    int nc = b >> 2;
    int n = nc / 3, c = nc % 3;
    int d = c * 512 + threadIdx.x * 4;
    const float* base = v + (size_t)n * PP * DD + (size_t)hh * PPC * DD + d;
    float ax = 0.f, ay = 0.f, az = 0.f, aw = 0.f;
#pragma unroll 8
    for (int p = 0; p < PPC; p++) {
        float4 x = *reinterpret_cast<const float4*>(base + (size_t)p * DD);
        ax += x.x; ay += x.y; az += x.z; aw += x.w;
    }
    float4 r = make_float4(ax, ay, az, aw);
    *reinterpret_cast<float4*>(&mp2[(size_t)hh * NF * DD + (size_t)n * DD + d]) = r;
}

// ---------------------------------------------------------------------------
// Chunked-parallel momentum EMA, emits hi/lo bf16 A operand directly.
// Chunk 7 also zero-pads row 127.
// ---------------------------------------------------------------------------
__device__ __forceinline__ float mp_mean(const float* mp2, int i, int d) {
    const float inv = 1.0f / (float)PP;
    float s = mp2[(size_t)i * DD + d];
#pragma unroll
    for (int h = 1; h < SPLIT; h++) s += mp2[(size_t)(h * NF + i) * DD + d];
    return s * inv;
}
__global__ void k_ema(const float* __restrict__ mp2,
                      __nv_bfloat16* __restrict__ hiA, __nv_bfloat16* __restrict__ loA) {
    int bx = blockIdx.x;
    int d = (bx >> 3) * 256 + threadIdx.x;
    int c = bx & 7;
    int s = c * 16;
    int w = s - 26; if (w < 0) w = 0;
    int e_end = min(s + 16, NM1);
    float prev = mp_mean(mp2, w, d);
    float e = 0.f;
    for (int i = w; i < e_end; i++) {
        float cur = mp_mean(mp2, i + 1, d);
        float diff = cur - prev;
        e = (i == w) ? diff : (0.5f * diff + 0.5f * e);
        if (i >= s) {
            __nv_bfloat16 h, l;
            split_bf16(e, h, l);
            hiA[(size_t)i * DD + d] = h;
            loA[(size_t)i * DD + d] = l;
        }
        prev = cur;
    }
    if (c == 7) {   // zero-pad row 127
        hiA[(size_t)NM1 * DD + d] = __float2bfloat16(0.f);
        loA[(size_t)NM1 * DD + d] = __float2bfloat16(0.f);
    }
}

// ---------------------------------------------------------------------------
// Bias init
// ---------------------------------------------------------------------------
__global__ void k_init_bias(float* __restrict__ C, const float* __restrict__ bias,
                            int total, int Nn) {
    int idx = blockIdx.x * blockDim.x + threadIdx.x;
    if (idx < total) C[idx] = bias[idx % Nn];
}

// ---------------------------------------------------------------------------
// bf16 mma.sync GEMM with FUSED fp32->hi/lo B conversion and 3-term split:
//   C += hiA@W + loA@W_hi_residual-structure  (hiA*hiB + loA*hiB + hiA*loB)
// A: pre-split hi/lo bf16 [128, 1536] K-major. B: original fp32 [K, Ntot].
// CTA: 256 thr = 8 warps (4M x 2N). Tile M=128 x N=64, BK=64.
// grid(Ntot/64, 1, S) split-K, Kcta multiple of 64. Atomic epilogue.
// ---------------------------------------------------------------------------
#define ASTR 72
__global__ __launch_bounds__(256, 1)
void k_gemm_fused(const __nv_bfloat16* __restrict__ hiA, const __nv_bfloat16* __restrict__ loA,
                  const float* __restrict__ B,
                  float* __restrict__ C, int M, int Ntot, int Kcta) {
    __shared__ __align__(16) __nv_bfloat16 Ah[128 * ASTR];
    __shared__ __align__(16) __nv_bfloat16 Al[128 * ASTR];
    __shared__ __align__(16) __nv_bfloat16 Bh[64 * ASTR];
    __shared__ __align__(16) __nv_bfloat16 Bl[64 * ASTR];

    const int tid = threadIdx.x;
    const int lane = tid & 31, wid = tid >> 5;
    const int wm = wid & 3, wn = wid >> 2;        // warp tile: 32M x 32N
    const int gid = lane >> 2, qd = lane & 3;
    const int n0 = blockIdx.x * 64;
    const int kb = blockIdx.z * Kcta;

    float acc[2][4][4];
#pragma unroll
    for (int i = 0; i < 2; i++)
#pragma unroll
        for (int j = 0; j < 4; j++)
#pragma unroll
            for (int q = 0; q < 4; q++) acc[i][j][q] = 0.f;

    for (int kc = kb; kc < kb + Kcta; kc += 64) {
        // A tiles: hi and lo, 128 x 64 bf16 each (uint4 = 8 bf16)
#pragma unroll
        for (int it = 0; it < 4; it++) {
            int g = tid + it * 256;
            int r = g >> 3, q = g & 7;
            *reinterpret_cast<uint4*>(&Ah[r * ASTR + q * 8]) =
                *reinterpret_cast<const uint4*>(hiA + (size_t)r * DD + kc + q * 8);
            *reinterpret_cast<uint4*>(&Al[r * ASTR + q * 8]) =
                *reinterpret_cast<const uint4*>(loA + (size_t)r * DD + kc + q * 8);
        }
        // B tile: 64k x 64n fp32 from [K, Ntot]; convert + transpose into smem
#pragma unroll
        for (int it = 0; it < 4; it++) {
            int g = tid + it * 256;              // 0..1023 float4s
            int k = g >> 4, nq = g & 15;
            float4 wv = *reinterpret_cast<const float4*>(B + (size_t)(kc + k) * Ntot + n0 + nq * 4);
            float vals[4] = {wv.x, wv.y, wv.z, wv.w};
#pragma unroll
            for (int j = 0; j < 4; j++) {
                __nv_bfloat16 h, l;
                split_bf16(vals[j], h, l);
                Bh[(nq * 4 + j) * ASTR + k] = h;
                Bl[(nq * 4 + j) * ASTR + k] = l;
            }
        }
        __syncthreads();

#pragma unroll
        for (int ks = 0; ks < 4; ks++) {
            const int cb = ks * 16 + qd * 2;
            uint32_t ah[2][4], al[2][4];
#pragma unroll
            for (int mt = 0; mt < 2; mt++) {
                int r0 = wm * 32 + mt * 16 + gid;
                ah[mt][0] = *reinterpret_cast<const uint32_t*>(&Ah[r0 * ASTR + cb]);
                ah[mt][1] = *reinterpret_cast<const uint32_t*>(&Ah[(r0 + 8) * ASTR + cb]);
                ah[mt][2] = *reinterpret_cast<const uint32_t*>(&Ah[r0 * ASTR + cb + 8]);
                ah[mt][3] = *reinterpret_cast<const uint32_t*>(&Ah[(r0 + 8) * ASTR + cb + 8]);
                al[mt][0] = *reinterpret_cast<const uint32_t*>(&Al[r0 * ASTR + cb]);
                al[mt][1] = *reinterpret_cast<const uint32_t*>(&Al[(r0 + 8) * ASTR + cb]);
                al[mt][2] = *reinterpret_cast<const uint32_t*>(&Al[r0 * ASTR + cb + 8]);
                al[mt][3] = *reinterpret_cast<const uint32_t*>(&Al[(r0 + 8) * ASTR + cb + 8]);
            }
            uint32_t bh[4][2], bl[4][2];
#pragma unroll
            for (int nt = 0; nt < 4; nt++) {
                int nn = wn * 32 + nt * 8 + gid;
                bh[nt][0] = *reinterpret_cast<const uint32_t*>(&Bh[nn * ASTR + cb]);
                bh[nt][1] = *reinterpret_cast<const uint32_t*>(&Bh[nn * ASTR + cb + 8]);
                bl[nt][0] = *reinterpret_cast<const uint32_t*>(&Bl[nn * ASTR + cb]);
                bl[nt][1] = *reinterpret_cast<const uint32_t*>(&Bl[nn * ASTR + cb + 8]);
            }
#pragma unroll
            for (int mt = 0; mt < 2; mt++)
#pragma unroll
                for (int nt = 0; nt < 4; nt++) {
                    asm volatile(
                        "mma.sync.aligned.m16n8k16.row.col.f32.bf16.bf16.f32 "
                        "{%0,%1,%2,%3}, {%4,%5,%6,%7}, {%8,%9}, {%0,%1,%2,%3};"
                        : "+f"(acc[mt][nt][0]), "+f"(acc[mt][nt][1]),
                          "+f"(acc[mt][nt][2]), "+f"(acc[mt][nt][3])
                        : "r"(ah[mt][0]), "r"(ah[mt][1]), "r"(ah[mt][2]), "r"(ah[mt][3]),
                          "r"(bh[nt][0]), "r"(bh[nt][1]));
                    asm volatile(
                        "mma.sync.aligned.m16n8k16.row.col.f32.bf16.bf16.f32 "
                        "{%0,%1,%2,%3}, {%4,%5,%6,%7}, {%8,%9}, {%0,%1,%2,%3};"
                        : "+f"(acc[mt][nt][0]), "+f"(acc[mt][nt][1]),
                          "+f"(acc[mt][nt][2]), "+f"(acc[mt][nt][3])
                        : "r"(al[mt][0]), "r"(al[mt][1]), "r"(al[mt][2]), "r"(al[mt][3]),
                          "r"(bh[nt][0]), "r"(bh[nt][1]));
                    asm volatile(
                        "mma.sync.aligned.m16n8k16.row.col.f32.bf16.bf16.f32 "
                        "{%0,%1,%2,%3}, {%4,%5,%6,%7}, {%8,%9}, {%0,%1,%2,%3};"
                        : "+f"(acc[mt][nt][0]), "+f"(acc[mt][nt][1]),
                          "+f"(acc[mt][nt][2]), "+f"(acc[mt][nt][3])
                        : "r"(ah[mt][0]), "r"(ah[mt][1]), "r"(ah[mt][2]), "r"(ah[mt][3]),
                          "r"(bl[nt][0]), "r"(bl[nt][1]));
                }
        }
        __syncthreads();
    }

    // Atomic epilogue (split-K partial sums)
#pragma unroll
    for (int mt = 0; mt < 2; mt++) {
        int r0 = wm * 32 + mt * 16 + gid;
#pragma unroll
        for (int nt = 0; nt < 4; nt++) {
            int cc = n0 + wn * 32 + nt * 8 + qd * 2;
            if (r0 < M) {
                atomicAdd(&C[(size_t)r0 * Ntot + cc],     acc[mt][nt][0]);
                atomicAdd(&C[(size_t)r0 * Ntot + cc + 1], acc[mt][nt][1]);
            }
            if (r0 + 8 < M) {
                atomicAdd(&C[(size_t)(r0 + 8) * Ntot + cc],     acc[mt][nt][2]);
                atomicAdd(&C[(size_t)(r0 + 8) * Ntot + cc + 1], acc[mt][nt][3]);
            }
        }
    }
}

// ---------------------------------------------------------------------------
// LayerNorm per row, emits hi/lo bf16 A operand. Block NM1 zero-pads row 127.
// ---------------------------------------------------------------------------
__global__ void k_ln(const float* __restrict__ X,
                     __nv_bfloat16* __restrict__ hiA, __nv_bfloat16* __restrict__ loA,
                     const float* __restrict__ gam, const float* __restrict__ bet) {
    int m = blockIdx.x;
    if (m == NM1) {       // padding row
        for (int d = threadIdx.x; d < DD; d += 256) {
            hiA[(size_t)m * DD + d] = __float2bfloat16(0.f);
            loA[(size_t)m * DD + d] = __float2bfloat16(0.f);
        }
        return;
    }
    const float* x = X + (size_t)m * DD;
    __shared__ float red[32];
    __shared__ float s_mu, s_rstd;

    float s = 0.f;
    for (int d = threadIdx.x; d < DD; d += 256) s += x[d];
    for (int o = 16; o; o >>= 1) s += __shfl_down_sync(0xffffffffu, s, o);
    int w = threadIdx.x >> 5, lane = threadIdx.x & 31;
    if (lane == 0) red[w] = s;
    __syncthreads();
    if (threadIdx.x == 0) {
        float t = 0.f;
        for (int i = 0; i < 8; i++) t += red[i];
        s_mu = t / (float)DD;
    }
    __syncthreads();
    float mu = s_mu;

    float s2 = 0.f;
    for (int d = threadIdx.x; d < DD; d += 256) {
        float v = x[d] - mu; s2 += v * v;
    }
    for (int o = 16; o; o >>= 1) s2 += __shfl_down_sync(0xffffffffu, s2, o);
    if (lane == 0) red[w] = s2;
    __syncthreads();
    if (threadIdx.x == 0) {
        float t = 0.f;
        for (int i = 0; i < 8; i++) t += red[i];
        s_rstd = rsqrtf(t / (float)DD + 1e-5f);
    }
    __syncthreads();
    float rstd = s_rstd;

    for (int d = threadIdx.x; d < DD; d += 256) {
        float yv = (x[d] - mu) * rstd * gam[d] + bet[d];
        __nv_bfloat16 h, l;
        split_bf16(yv, h, l);
        hiA[(size_t)m * DD + d] = h;
        loA[(size_t)m * DD + d] = l;
    }
}

// ---------------------------------------------------------------------------
// Gate head with fused exact GELU + Gumbel softmax y
// ---------------------------------------------------------------------------
__global__ void k_gate(const float* __restrict__ H, const float* __restrict__ W2,
                       const float* __restrict__ b2, const float* __restrict__ gu,
                       float* __restrict__ out_gate, float* __restrict__ y) {
    int m = blockIdx.x;
    const float* h = H + (size_t)m * DD;
    float a0 = 0.f, a1 = 0.f;
    for (int k = threadIdx.x; k < DD; k += 128) {
        float hr = h[k];
        float hv = 0.5f * hr * (1.f + erff(hr * 0.70710678118654752440f));
        a0 += hv * W2[2 * k + 0];
        a1 += hv * W2[2 * k + 1];
    }
    for (int o = 16; o; o >>= 1) {
        a0 += __shfl_down_sync(0xffffffffu, a0, o);
        a1 += __shfl_down_sync(0xffffffffu, a1, o);
    }
    __shared__ float r0[4], r1[4];
    int w = threadIdx.x >> 5, lane = threadIdx.x & 31;
    if (lane == 0) { r0[w] = a0; r1[w] = a1; }
    __syncthreads();
    if (threadIdx.x == 0) {
        float l0 = r0[0] + r0[1] + r0[2] + r0[3] + b2[0];
        float l1 = r1[0] + r1[1] + r1[2] + r1[3] + b2[1];
        out_gate[2 * m + 0] = l0;
        out_gate[2 * m + 1] = l1;
        float u0 = gu[2 * m + 0], u1 = gu[2 * m + 1];
        float g0 = -logf(-logf(u0 + 1e-20f) + 1e-20f);
        float g1 = -logf(-logf(u1 + 1e-20f) + 1e-20f);
        float s0 = (l0 + 0.1f * g0) * 2.0f;
        float s1 = (l1 + 0.1f * g1) * 2.0f;
        y[m] = 1.0f / (1.0f + expf(s0 - s1));
    }
}

// ---------------------------------------------------------------------------
// Parallel top-8 of 127 + z_hard + selection list
// ---------------------------------------------------------------------------
__global__ void k_topk(const float* __restrict__ y, float* __restrict__ out_z) {
    __shared__ float sv[128];
    __shared__ int   si[128];
    int tid = threadIdx.x;
    float val = (tid < NM1) ? y[tid] : -1e30f;
    if (tid == 0) { out_z[0] = 1.f; g_sel[0] = 0; }
    if (tid < NM1) out_z[tid + 1] = 0.f;
    __syncthreads();
    for (int r = 0; r < NC; r++) {
        sv[tid] = val; si[tid] = tid;
        __syncthreads();
        for (int o = 64; o; o >>= 1) {
            if (tid < o) {
                float ov = sv[tid + o]; int oi = si[tid + o];
                if (ov > sv[tid] || (ov == sv[tid] && oi < si[tid])) {
                    sv[tid] = ov; si[tid] = oi;
                }
            }
            __syncthreads();
        }
        int wn = si[0];
        if (tid == wn) val = -1e30f;
        if (tid == 0) { g_sel[r + 1] = wn + 1; out_z[wn + 1] = 1.f; }
        __syncthreads();
    }
}

// ---------------------------------------------------------------------------
// Pooled thumbnail features from 9 selected frames, emits hi/lo bf16 rows
// 0..63; blocks 192..383 zero-pad rows 64..127.
// ---------------------------------------------------------------------------
__global__ void k_pool(const float* __restrict__ v,
                       __nv_bfloat16* __restrict__ hiA, __nv_bfloat16* __restrict__ loA) {
    int b = blockIdx.x;
    if (b >= NQk * 3) {                 // padding rows 64..127
        int b2 = b - NQk * 3;
        int q = NQk + b2 / 3, c = b2 % 3;
        int d = c * 512 + threadIdx.x * 4;
        for (int j = 0; j < 4; j++) {
            hiA[(size_t)q * DD + d + j] = __float2bfloat16(0.f);
            loA[(size_t)q * DD + d + j] = __float2bfloat16(0.f);
        }
        return;
    }
    int q = b / 3, c = b % 3;
    int d = c * 512 + threadIdx.x * 4;
    float ax = 0.f, ay = 0.f, az = 0.f, aw = 0.f;
    for (int s = 0; s <= NC; s++) {
        int f = g_sel[s];
        const float* base = v + ((size_t)f * PP + q * 9) * DD + d;
#pragma unroll
        for (int p = 0; p < 9; p++) {
            float4 x = *reinterpret_cast<const float4*>(base + (size_t)p * DD);
            ax += x.x; ay += x.y; az += x.z; aw += x.w;
        }
    }
    const float inv = 1.0f / 81.0f;
    float vals[4] = {ax * inv, ay * inv, az * inv, aw * inv};
#pragma unroll
    for (int j = 0; j < 4; j++) {
        __nv_bfloat16 h, l;
        split_bf16(vals[j], h, l);
        hiA[(size_t)q * DD + d + j] = h;
        loA[(size_t)q * DD + d + j] = l;
    }
}

// ---------------------------------------------------------------------------
// Launch
// ---------------------------------------------------------------------------
extern "C" void kernel_launch(void* const* d_in, const int* in_sizes, int n_in,
                              void* d_out, int out_size) {
    const float* v     = (const float*)d_in[0];
    const float* gu    = (const float*)d_in[1];
    const float* W_agg = (const float*)d_in[2];
    const float* b_agg = (const float*)d_in[3];
    const float* ln_g  = (const float*)d_in[4];
    const float* ln_b  = (const float*)d_in[5];
    const float* W1    = (const float*)d_in[6];
    const float* b1    = (const float*)d_in[7];
    const float* W2    = (const float*)d_in[8];
    const float* b2    = (const float*)d_in[9];
    const float* W_th  = (const float*)d_in[10];
    const float* b_th  = (const float*)d_in[11];

    float* out       = (float*)d_out;
    float* out_gate  = out;
    float* out_thumb = out + NM1 * 2;
    float* out_z     = out_thumb + NQk * LMq;

    float* scr = nullptr;
    cudaGetSymbolAddress((void**)&scr, g_scratch);
    float* mp2  = scr + OFF_MP;
    float* feat = scr + OFF_FEAT;
    float* h    = scr + OFF_H;
    float* yv   = scr + OFF_Y;

    __nv_bfloat16 *hiA, *loA;
    cudaGetSymbolAddress((void**)&hiA, g_hiA);
    cudaGetSymbolAddress((void**)&loA, g_loA);

    // Patch sums + EMA (EMA emits hi/lo A directly)
    k_mp<<<NF * 3 * SPLIT, 128>>>(v, mp2);
    k_ema<<<(DD / 256) * 8, 256>>>(mp2, hiA, loA);

    // GEMM1: feat = ema @ W_agg + b_agg  (B converted in-kernel)
    k_init_bias<<<(NM1 * DD + 255) / 256, 256>>>(feat, b_agg, NM1 * DD, DD);
    {
        dim3 grid(DD / 64, 1, 6);
        k_gemm_fused<<<grid, 256>>>(hiA, loA, W_agg, feat, NM1, DD, DD / 6);
    }

    // LayerNorm (emits hi/lo A for GEMM2)
    k_ln<<<NM1 + 1, 256>>>(feat, hiA, loA, ln_g, ln_b);

    // GEMM2: h = xn @ W1 + b1  (GELU fused into gate)
    k_init_bias<<<(NM1 * DD + 255) / 256, 256>>>(h, b1, NM1 * DD, DD);
    {
        dim3 grid(DD / 64, 1, 6);
        k_gemm_fused<<<grid, 256>>>(hiA, loA, W1, h, NM1, DD, DD / 6);
    }

    // gate + topk + pool (pool emits hi/lo A for GEMM3)
    k_gate<<<NM1, 128>>>(h, W2, b2, gu, out_gate, yv);
    k_topk<<<1, 128>>>(yv, out_z);
    k_pool<<<NQk * 3 * 2, 128>>>(v, hiA, loA);

    // GEMM3: thumbnail = pooled @ W_th + b_th
    k_init_bias<<<(NQk * LMq + 255) / 256, 256>>>(out_thumb, b_th, NQk * LMq, LMq);
    {
        dim3 grid(LMq / 64, 1, 3);
        k_gemm_fused<<<grid, 256>>>(hiA, loA, W_th, out_thumb, NQk, LMq, DD / 3);
    }
}

// round 8
// speedup vs baseline: 1.5992x; 1.0667x over previous
#include <cuda_runtime.h>
#include <cuda_bf16.h>
#include <math.h>
#include <cstdint>

// Problem constants
#define NF   128
#define PP   576
#define DD   1536
#define LMq  4096
#define NQk  64
#define NM1  127
#define NC   8
#define SPLIT 4
#define PPC  (PP/SPLIT)

// Float scratch
#define OFF_MP    0
#define OFF_FEAT  (SPLIT*NF*DD)
#define OFF_H     (OFF_FEAT + NM1*DD)
#define OFF_Y     (OFF_H    + NM1*DD)
#define SCRATCH_TOTAL (OFF_Y + 256)

__device__ float g_scratch[SCRATCH_TOTAL];
__device__ int   g_sel[NC + 1];

// bf16 hi/lo A operand (padded to 128 rows), written directly by producers
__device__ __align__(16) __nv_bfloat16 g_hiA[128 * DD];
__device__ __align__(16) __nv_bfloat16 g_loA[128 * DD];

__device__ __forceinline__ void split_bf16(float a, __nv_bfloat16& h, __nv_bfloat16& l) {
    h = __float2bfloat16(a);
    l = __float2bfloat16(a - __bfloat162float(h));
}

__device__ __forceinline__ void cpa16(uint32_t dst, const void* src) {
    asm volatile("cp.async.cg.shared.global [%0], [%1], 16;" :: "r"(dst), "l"(src));
}

// ---------------------------------------------------------------------------
// Patch partial sums
// ---------------------------------------------------------------------------
__global__ void k_mp(const float* __restrict__ v, float* __restrict__ mp2) {
    int b = blockIdx.x;
    int hh = b & (SPLIT - 1);
    int nc = b >> 2;
    int n = nc / 3, c = nc % 3;
    int d = c * 512 + threadIdx.x * 4;
    const float* base = v + (size_t)n * PP * DD + (size_t)hh * PPC * DD + d;
    float ax = 0.f, ay = 0.f, az = 0.f, aw = 0.f;
#pragma unroll 8
    for (int p = 0; p < PPC; p++) {
        float4 x = *reinterpret_cast<const float4*>(base + (size_t)p * DD);
        ax += x.x; ay += x.y; az += x.z; aw += x.w;
    }
    float4 r = make_float4(ax, ay, az, aw);
    *reinterpret_cast<float4*>(&mp2[(size_t)hh * NF * DD + (size_t)n * DD + d]) = r;
}

// ---------------------------------------------------------------------------
// Chunked-parallel momentum EMA -> hi/lo bf16 A operand
// ---------------------------------------------------------------------------
__device__ __forceinline__ float mp_mean(const float* mp2, int i, int d) {
    const float inv = 1.0f / (float)PP;
    float s = mp2[(size_t)i * DD + d];
#pragma unroll
    for (int h = 1; h < SPLIT; h++) s += mp2[(size_t)(h * NF + i) * DD + d];
    return s * inv;
}
__global__ void k_ema(const float* __restrict__ mp2,
                      __nv_bfloat16* __restrict__ hiA, __nv_bfloat16* __restrict__ loA) {
    int bx = blockIdx.x;
    int d = (bx >> 3) * 256 + threadIdx.x;
    int c = bx & 7;
    int s = c * 16;
    int w = s - 26; if (w < 0) w = 0;
    int e_end = min(s + 16, NM1);
    float prev = mp_mean(mp2, w, d);
    float e = 0.f;
    for (int i = w; i < e_end; i++) {
        float cur = mp_mean(mp2, i + 1, d);
        float diff = cur - prev;
        e = (i == w) ? diff : (0.5f * diff + 0.5f * e);
        if (i >= s) {
            __nv_bfloat16 h, l;
            split_bf16(e, h, l);
            hiA[(size_t)i * DD + d] = h;
            loA[(size_t)i * DD + d] = l;
        }
        prev = cur;
    }
    if (c == 7) {
        hiA[(size_t)NM1 * DD + d] = __float2bfloat16(0.f);
        loA[(size_t)NM1 * DD + d] = __float2bfloat16(0.f);
    }
}

// ---------------------------------------------------------------------------
// Bias init
// ---------------------------------------------------------------------------
__global__ void k_init_bias(float* __restrict__ C, const float* __restrict__ bias,
                            int total, int Nn) {
    int idx = blockIdx.x * blockDim.x + threadIdx.x;
    if (idx < total) C[idx] = bias[idx % Nn];
}

// ---------------------------------------------------------------------------
// Pipelined bf16 mma.sync GEMM with fused fp32->hi/lo B conversion, 3-term:
//   C += hiA*hiB + loA*hiB + hiA*loB
// BK=32, 2-stage cp.async pipeline for A, reg-prefetch + convert for B.
// CTA: 256 thr = 8 warps (4M x 2N); tile M=128 x N=64; split-K atomics.
// Dynamic smem: 2 stages x (Ah,Al 128x40 + Bh,Bl 64x40) bf16 = 60KB.
// ---------------------------------------------------------------------------
#define BK   32
#define ASTR 40
#define GEMM_SMEM (2*(2*128*ASTR + 2*64*ASTR)*2)

__global__ __launch_bounds__(256, 2)
void k_gemm_fused(const __nv_bfloat16* __restrict__ hiA, const __nv_bfloat16* __restrict__ loA,
                  const float* __restrict__ B,
                  float* __restrict__ C, int M, int Ntot, int Kcta) {
    extern __shared__ __align__(16) unsigned char dyn[];
    // layout (bf16 counts): stage s: Ah at s*(2*128*ASTR), Al follows;
    // B region after both A stages.
    __nv_bfloat16* Ahs[2];
    __nv_bfloat16* Als[2];
    __nv_bfloat16* Bhs[2];
    __nv_bfloat16* Bls[2];
    {
        __nv_bfloat16* p = reinterpret_cast<__nv_bfloat16*>(dyn);
        Ahs[0] = p;                    Als[0] = Ahs[0] + 128 * ASTR;
        Ahs[1] = Als[0] + 128 * ASTR;  Als[1] = Ahs[1] + 128 * ASTR;
        Bhs[0] = Als[1] + 128 * ASTR;  Bls[0] = Bhs[0] + 64 * ASTR;
        Bhs[1] = Bls[0] + 64 * ASTR;   Bls[1] = Bhs[1] + 64 * ASTR;
    }

    const int tid = threadIdx.x;
    const int lane = tid & 31, wid = tid >> 5;
    const int wm = wid & 3, wn = wid >> 2;
    const int gid = lane >> 2, qd = lane & 3;
    const int n0 = blockIdx.x * 64;
    const int kb = blockIdx.z * Kcta;

    float acc[2][4][4];
#pragma unroll
    for (int i = 0; i < 2; i++)
#pragma unroll
        for (int j = 0; j < 4; j++)
#pragma unroll
            for (int q = 0; q < 4; q++) acc[i][j][q] = 0.f;

    const int a_r = tid >> 2, a_q = tid & 3;           // +128 rows via it
    const int b_k = tid >> 4, b_nq = tid & 15;         // +32 k via it? no: 512 float4s

    float4 breg[2];

    auto loadA = [&](int kc, int s) {
#pragma unroll
        for (int it = 0; it < 2; it++) {
            int r = a_r + it * 64;
            uint32_t dh = (uint32_t)__cvta_generic_to_shared(Ahs[s] + r * ASTR + a_q * 8);
            cpa16(dh, hiA + (size_t)r * DD + kc + a_q * 8);
            uint32_t dl = (uint32_t)__cvta_generic_to_shared(Als[s] + r * ASTR + a_q * 8);
            cpa16(dl, loA + (size_t)r * DD + kc + a_q * 8);
        }
        asm volatile("cp.async.commit_group;" ::: "memory");
    };
    auto loadBreg = [&](int kc) {
#pragma unroll
        for (int it = 0; it < 2; it++) {
            int g = tid + it * 256;
            int k = g >> 4, nq = g & 15;
            breg[it] = *reinterpret_cast<const float4*>(B + (size_t)(kc + k) * Ntot + n0 + nq * 4);
        }
    };
    auto storeB = [&](int s) {
#pragma unroll
        for (int it = 0; it < 2; it++) {
            int g = tid + it * 256;
            int k = g >> 4, nq = g & 15;
            float vals[4] = {breg[it].x, breg[it].y, breg[it].z, breg[it].w};
#pragma unroll
            for (int j = 0; j < 4; j++) {
                __nv_bfloat16 h, l;
                split_bf16(vals[j], h, l);
                Bhs[s][(nq * 4 + j) * ASTR + k] = h;
                Bls[s][(nq * 4 + j) * ASTR + k] = l;
            }
        }
    };
    auto compute = [&](int s) {
        const __nv_bfloat16* Ah = Ahs[s];
        const __nv_bfloat16* Al = Als[s];
        const __nv_bfloat16* Bh = Bhs[s];
        const __nv_bfloat16* Bl = Bls[s];
#pragma unroll
        for (int ks = 0; ks < 2; ks++) {
            const int cb = ks * 16 + qd * 2;
            uint32_t ah[2][4], al[2][4];
#pragma unroll
            for (int mt = 0; mt < 2; mt++) {
                int r0 = wm * 32 + mt * 16 + gid;
                ah[mt][0] = *reinterpret_cast<const uint32_t*>(&Ah[r0 * ASTR + cb]);
                ah[mt][1] = *reinterpret_cast<const uint32_t*>(&Ah[(r0 + 8) * ASTR + cb]);
                ah[mt][2] = *reinterpret_cast<const uint32_t*>(&Ah[r0 * ASTR + cb + 8]);
                ah[mt][3] = *reinterpret_cast<const uint32_t*>(&Ah[(r0 + 8) * ASTR + cb + 8]);
                al[mt][0] = *reinterpret_cast<const uint32_t*>(&Al[r0 * ASTR + cb]);
                al[mt][1] = *reinterpret_cast<const uint32_t*>(&Al[(r0 + 8) * ASTR + cb]);
                al[mt][2] = *reinterpret_cast<const uint32_t*>(&Al[r0 * ASTR + cb + 8]);
                al[mt][3] = *reinterpret_cast<const uint32_t*>(&Al[(r0 + 8) * ASTR + cb + 8]);
            }
            uint32_t bh[4][2], bl[4][2];
#pragma unroll
            for (int nt = 0; nt < 4; nt++) {
                int nn = wn * 32 + nt * 8 + gid;
                bh[nt][0] = *reinterpret_cast<const uint32_t*>(&Bh[nn * ASTR + cb]);
                bh[nt][1] = *reinterpret_cast<const uint32_t*>(&Bh[nn * ASTR + cb + 8]);
                bl[nt][0] = *reinterpret_cast<const uint32_t*>(&Bl[nn * ASTR + cb]);
                bl[nt][1] = *reinterpret_cast<const uint32_t*>(&Bl[nn * ASTR + cb + 8]);
            }
#pragma unroll
            for (int mt = 0; mt < 2; mt++)
#pragma unroll
                for (int nt = 0; nt < 4; nt++) {
                    asm volatile(
                        "mma.sync.aligned.m16n8k16.row.col.f32.bf16.bf16.f32 "
                        "{%0,%1,%2,%3}, {%4,%5,%6,%7}, {%8,%9}, {%0,%1,%2,%3};"
                        : "+f"(acc[mt][nt][0]), "+f"(acc[mt][nt][1]),
                          "+f"(acc[mt][nt][2]), "+f"(acc[mt][nt][3])
                        : "r"(ah[mt][0]), "r"(ah[mt][1]), "r"(ah[mt][2]), "r"(ah[mt][3]),
                          "r"(bh[nt][0]), "r"(bh[nt][1]));
                    asm volatile(
                        "mma.sync.aligned.m16n8k16.row.col.f32.bf16.bf16.f32 "
                        "{%0,%1,%2,%3}, {%4,%5,%6,%7}, {%8,%9}, {%0,%1,%2,%3};"
                        : "+f"(acc[mt][nt][0]), "+f"(acc[mt][nt][1]),
                          "+f"(acc[mt][nt][2]), "+f"(acc[mt][nt][3])
                        : "r"(al[mt][0]), "r"(al[mt][1]), "r"(al[mt][2]), "r"(al[mt][3]),
                          "r"(bh[nt][0]), "r"(bh[nt][1]));
                    asm volatile(
                        "mma.sync.aligned.m16n8k16.row.col.f32.bf16.bf16.f32 "
                        "{%0,%1,%2,%3}, {%4,%5,%6,%7}, {%8,%9}, {%0,%1,%2,%3};"
                        : "+f"(acc[mt][nt][0]), "+f"(acc[mt][nt][1]),
                          "+f"(acc[mt][nt][2]), "+f"(acc[mt][nt][3])
                        : "r"(ah[mt][0]), "r"(ah[mt][1]), "r"(ah[mt][2]), "r"(ah[mt][3]),
                          "r"(bl[nt][0]), "r"(bl[nt][1]));
                }
        }
    };

    // Prologue: fill stage 0
    loadA(kb, 0);
    loadBreg(kb);
    storeB(0);
    asm volatile("cp.async.wait_group 0;" ::: "memory");
    __syncthreads();

    int cur = 0;
    for (int kc = kb; kc < kb + Kcta; kc += BK) {
        bool has = (kc + BK) < (kb + Kcta);
        if (has) {
            loadA(kc + BK, cur ^ 1);
            loadBreg(kc + BK);
        }
        compute(cur);
        if (has) {
            storeB(cur ^ 1);
            asm volatile("cp.async.wait_group 0;" ::: "memory");
            __syncthreads();
        }
        cur ^= 1;
    }

    // Atomic epilogue (split-K partial sums)
#pragma unroll
    for (int mt = 0; mt < 2; mt++) {
        int r0 = wm * 32 + mt * 16 + gid;
#pragma unroll
        for (int nt = 0; nt < 4; nt++) {
            int cc = n0 + wn * 32 + nt * 8 + qd * 2;
            if (r0 < M) {
                atomicAdd(&C[(size_t)r0 * Ntot + cc],     acc[mt][nt][0]);
                atomicAdd(&C[(size_t)r0 * Ntot + cc + 1], acc[mt][nt][1]);
            }
            if (r0 + 8 < M) {
                atomicAdd(&C[(size_t)(r0 + 8) * Ntot + cc],     acc[mt][nt][2]);
                atomicAdd(&C[(size_t)(r0 + 8) * Ntot + cc + 1], acc[mt][nt][3]);
            }
        }
    }
}

// ---------------------------------------------------------------------------
// LayerNorm per row -> hi/lo bf16. Block NM1 zero-pads row 127.
// ---------------------------------------------------------------------------
__global__ void k_ln(const float* __restrict__ X,
                     __nv_bfloat16* __restrict__ hiA, __nv_bfloat16* __restrict__ loA,
                     const float* __restrict__ gam, const float* __restrict__ bet) {
    int m = blockIdx.x;
    if (m == NM1) {
        for (int d = threadIdx.x; d < DD; d += 256) {
            hiA[(size_t)m * DD + d] = __float2bfloat16(0.f);
            loA[(size_t)m * DD + d] = __float2bfloat16(0.f);
        }
        return;
    }
    const float* x = X + (size_t)m * DD;
    __shared__ float red[32];
    __shared__ float s_mu, s_rstd;

    float s = 0.f;
    for (int d = threadIdx.x; d < DD; d += 256) s += x[d];
    for (int o = 16; o; o >>= 1) s += __shfl_down_sync(0xffffffffu, s, o);
    int w = threadIdx.x >> 5, lane = threadIdx.x & 31;
    if (lane == 0) red[w] = s;
    __syncthreads();
    if (threadIdx.x == 0) {
        float t = 0.f;
        for (int i = 0; i < 8; i++) t += red[i];
        s_mu = t / (float)DD;
    }
    __syncthreads();
    float mu = s_mu;

    float s2 = 0.f;
    for (int d = threadIdx.x; d < DD; d += 256) {
        float v = x[d] - mu; s2 += v * v;
    }
    for (int o = 16; o; o >>= 1) s2 += __shfl_down_sync(0xffffffffu, s2, o);
    if (lane == 0) red[w] = s2;
    __syncthreads();
    if (threadIdx.x == 0) {
        float t = 0.f;
        for (int i = 0; i < 8; i++) t += red[i];
        s_rstd = rsqrtf(t / (float)DD + 1e-5f);
    }
    __syncthreads();
    float rstd = s_rstd;

    for (int d = threadIdx.x; d < DD; d += 256) {
        float yv = (x[d] - mu) * rstd * gam[d] + bet[d];
        __nv_bfloat16 h, l;
        split_bf16(yv, h, l);
        hiA[(size_t)m * DD + d] = h;
        loA[(size_t)m * DD + d] = l;
    }
}

// ---------------------------------------------------------------------------
// Gate head with fused exact GELU + Gumbel softmax y
// ---------------------------------------------------------------------------
__global__ void k_gate(const float* __restrict__ H, const float* __restrict__ W2,
                       const float* __restrict__ b2, const float* __restrict__ gu,
                       float* __restrict__ out_gate, float* __restrict__ y) {
    int m = blockIdx.x;
    const float* h = H + (size_t)m * DD;
    float a0 = 0.f, a1 = 0.f;
    for (int k = threadIdx.x; k < DD; k += 128) {
        float hr = h[k];
        float hv = 0.5f * hr * (1.f + erff(hr * 0.70710678118654752440f));
        a0 += hv * W2[2 * k + 0];
        a1 += hv * W2[2 * k + 1];
    }
    for (int o = 16; o; o >>= 1) {
        a0 += __shfl_down_sync(0xffffffffu, a0, o);
        a1 += __shfl_down_sync(0xffffffffu, a1, o);
    }
    __shared__ float r0[4], r1[4];
    int w = threadIdx.x >> 5, lane = threadIdx.x & 31;
    if (lane == 0) { r0[w] = a0; r1[w] = a1; }
    __syncthreads();
    if (threadIdx.x == 0) {
        float l0 = r0[0] + r0[1] + r0[2] + r0[3] + b2[0];
        float l1 = r1[0] + r1[1] + r1[2] + r1[3] + b2[1];
        out_gate[2 * m + 0] = l0;
        out_gate[2 * m + 1] = l1;
        float u0 = gu[2 * m + 0], u1 = gu[2 * m + 1];
        float g0 = -logf(-logf(u0 + 1e-20f) + 1e-20f);
        float g1 = -logf(-logf(u1 + 1e-20f) + 1e-20f);
        float s0 = (l0 + 0.1f * g0) * 2.0f;
        float s1 = (l1 + 0.1f * g1) * 2.0f;
        y[m] = 1.0f / (1.0f + expf(s0 - s1));
    }
}

// ---------------------------------------------------------------------------
// Parallel top-8 of 127 + z_hard + selection list
// ---------------------------------------------------------------------------
__global__ void k_topk(const float* __restrict__ y, float* __restrict__ out_z) {
    __shared__ float sv[128];
    __shared__ int   si[128];
    int tid = threadIdx.x;
    float val = (tid < NM1) ? y[tid] : -1e30f;
    if (tid == 0) { out_z[0] = 1.f; g_sel[0] = 0; }
    if (tid < NM1) out_z[tid + 1] = 0.f;
    __syncthreads();
    for (int r = 0; r < NC; r++) {
        sv[tid] = val; si[tid] = tid;
        __syncthreads();
        for (int o = 64; o; o >>= 1) {
            if (tid < o) {
                float ov = sv[tid + o]; int oi = si[tid + o];
                if (ov > sv[tid] || (ov == sv[tid] && oi < si[tid])) {
                    sv[tid] = ov; si[tid] = oi;
                }
            }
            __syncthreads();
        }
        int wn = si[0];
        if (tid == wn) val = -1e30f;
        if (tid == 0) { g_sel[r + 1] = wn + 1; out_z[wn + 1] = 1.f; }
        __syncthreads();
    }
}

// ---------------------------------------------------------------------------
// Pooled thumbnail features -> hi/lo bf16 rows 0..63; pad rows 64..127
// ---------------------------------------------------------------------------
__global__ void k_pool(const float* __restrict__ v,
                       __nv_bfloat16* __restrict__ hiA, __nv_bfloat16* __restrict__ loA) {
    int b = blockIdx.x;
    if (b >= NQk * 3) {
        int b2 = b - NQk * 3;
        int q = NQk + b2 / 3, c = b2 % 3;
        int d = c * 512 + threadIdx.x * 4;
        for (int j = 0; j < 4; j++) {
            hiA[(size_t)q * DD + d + j] = __float2bfloat16(0.f);
            loA[(size_t)q * DD + d + j] = __float2bfloat16(0.f);
        }
        return;
    }
    int q = b / 3, c = b % 3;
    int d = c * 512 + threadIdx.x * 4;
    float ax = 0.f, ay = 0.f, az = 0.f, aw = 0.f;
    for (int s = 0; s <= NC; s++) {
        int f = g_sel[s];
        const float* base = v + ((size_t)f * PP + q * 9) * DD + d;
#pragma unroll
        for (int p = 0; p < 9; p++) {
            float4 x = *reinterpret_cast<const float4*>(base + (size_t)p * DD);
            ax += x.x; ay += x.y; az += x.z; aw += x.w;
        }
    }
    const float inv = 1.0f / 81.0f;
    float vals[4] = {ax * inv, ay * inv, az * inv, aw * inv};
#pragma unroll
    for (int j = 0; j < 4; j++) {
        __nv_bfloat16 h, l;
        split_bf16(vals[j], h, l);
        hiA[(size_t)q * DD + d + j] = h;
        loA[(size_t)q * DD + d + j] = l;
    }
}

// ---------------------------------------------------------------------------
// Launch
// ---------------------------------------------------------------------------
extern "C" void kernel_launch(void* const* d_in, const int* in_sizes, int n_in,
                              void* d_out, int out_size) {
    const float* v     = (const float*)d_in[0];
    const float* gu    = (const float*)d_in[1];
    const float* W_agg = (const float*)d_in[2];
    const float* b_agg = (const float*)d_in[3];
    const float* ln_g  = (const float*)d_in[4];
    const float* ln_b  = (const float*)d_in[5];
    const float* W1    = (const float*)d_in[6];
    const float* b1    = (const float*)d_in[7];
    const float* W2    = (const float*)d_in[8];
    const float* b2    = (const float*)d_in[9];
    const float* W_th  = (const float*)d_in[10];
    const float* b_th  = (const float*)d_in[11];

    float* out       = (float*)d_out;
    float* out_gate  = out;
    float* out_thumb = out + NM1 * 2;
    float* out_z     = out_thumb + NQk * LMq;

    float* scr = nullptr;
    cudaGetSymbolAddress((void**)&scr, g_scratch);
    float* mp2  = scr + OFF_MP;
    float* feat = scr + OFF_FEAT;
    float* h    = scr + OFF_H;
    float* yv   = scr + OFF_Y;

    __nv_bfloat16 *hiA, *loA;
    cudaGetSymbolAddress((void**)&hiA, g_hiA);
    cudaGetSymbolAddress((void**)&loA, g_loA);

    cudaFuncSetAttribute(k_gemm_fused, cudaFuncAttributeMaxDynamicSharedMemorySize, GEMM_SMEM);

    // Patch sums + EMA (EMA emits hi/lo A directly)
    k_mp<<<NF * 3 * SPLIT, 128>>>(v, mp2);
    k_ema<<<(DD / 256) * 8, 256>>>(mp2, hiA, loA);

    // GEMM1: feat = ema @ W_agg + b_agg
    k_init_bias<<<(NM1 * DD + 255) / 256, 256>>>(feat, b_agg, NM1 * DD, DD);
    {
        dim3 grid(DD / 64, 1, 12);
        k_gemm_fused<<<grid, 256, GEMM_SMEM>>>(hiA, loA, W_agg, feat, NM1, DD, DD / 12);
    }

    // LayerNorm (emits hi/lo A for GEMM2)
    k_ln<<<NM1 + 1, 256>>>(feat, hiA, loA, ln_g, ln_b);

    // GEMM2: h = xn @ W1 + b1  (GELU fused into gate)
    k_init_bias<<<(NM1 * DD + 255) / 256, 256>>>(h, b1, NM1 * DD, DD);
    {
        dim3 grid(DD / 64, 1, 12);
        k_gemm_fused<<<grid, 256, GEMM_SMEM>>>(hiA, loA, W1, h, NM1, DD, DD / 12);
    }

    // gate + topk + pool
    k_gate<<<NM1, 128>>>(h, W2, b2, gu, out_gate, yv);
    k_topk<<<1, 128>>>(yv, out_z);
    k_pool<<<NQk * 3 * 2, 128>>>(v, hiA, loA);

    // GEMM3: thumbnail = pooled @ W_th + b_th
    k_init_bias<<<(NQk * LMq + 255) / 256, 256>>>(out_thumb, b_th, NQk * LMq, LMq);
    {
        dim3 grid(LMq / 64, 1, 6);
        k_gemm_fused<<<grid, 256, GEMM_SMEM>>>(hiA, loA, W_th, out_thumb, NQk, LMq, DD / 6);
    }
}

// round 9
// speedup vs baseline: 1.7541x; 1.0968x over previous
#include <cuda_runtime.h>
#include <cuda_bf16.h>
#include <math.h>
#include <cstdint>

// Problem constants
#define NF   128
#define PP   576
#define DD   1536
#define LMq  4096
#define NQk  64
#define NM1  127
#define NC   8
#define SPLIT 4
#define PPC  (PP/SPLIT)

// Float scratch
#define OFF_MP    0
#define OFF_FEAT  (SPLIT*NF*DD)
#define OFF_H     (OFF_FEAT + NM1*DD)
#define OFF_Y     (OFF_H    + NM1*DD)
#define SCRATCH_TOTAL (OFF_Y + 256)

__device__ float g_scratch[SCRATCH_TOTAL];
__device__ int   g_sel[NC + 1];

__device__ __align__(16) __nv_bfloat16 g_hiA[128 * DD];
__device__ __align__(16) __nv_bfloat16 g_loA[128 * DD];

__device__ __forceinline__ void split_bf16(float a, __nv_bfloat16& h, __nv_bfloat16& l) {
    h = __float2bfloat16(a);
    l = __float2bfloat16(a - __bfloat162float(h));
}
__device__ __forceinline__ void cpa16(uint32_t dst, const void* src) {
    asm volatile("cp.async.cg.shared.global [%0], [%1], 16;" :: "r"(dst), "l"(src));
}
__device__ __forceinline__ void ldsm_x4(uint32_t* r, uint32_t addr) {
    asm volatile("ldmatrix.sync.aligned.m8n8.x4.shared.b16 {%0,%1,%2,%3}, [%4];"
        : "=r"(r[0]), "=r"(r[1]), "=r"(r[2]), "=r"(r[3]) : "r"(addr));
}
__device__ __forceinline__ void ldsm_x4t(uint32_t* r, uint32_t addr) {
    asm volatile("ldmatrix.sync.aligned.m8n8.x4.trans.shared.b16 {%0,%1,%2,%3}, [%4];"
        : "=r"(r[0]), "=r"(r[1]), "=r"(r[2]), "=r"(r[3]) : "r"(addr));
}

// ---------------------------------------------------------------------------
// Patch partial sums
// ---------------------------------------------------------------------------
__global__ void k_mp(const float* __restrict__ v, float* __restrict__ mp2) {
    int b = blockIdx.x;
    int hh = b & (SPLIT - 1);
    int nc = b >> 2;
    int n = nc / 3, c = nc % 3;
    int d = c * 512 + threadIdx.x * 4;
    const float* base = v + (size_t)n * PP * DD + (size_t)hh * PPC * DD + d;
    float ax = 0.f, ay = 0.f, az = 0.f, aw = 0.f;
#pragma unroll 8
    for (int p = 0; p < PPC; p++) {
        float4 x = *reinterpret_cast<const float4*>(base + (size_t)p * DD);
        ax += x.x; ay += x.y; az += x.z; aw += x.w;
    }
    float4 r = make_float4(ax, ay, az, aw);
    *reinterpret_cast<float4*>(&mp2[(size_t)hh * NF * DD + (size_t)n * DD + d]) = r;
}

// ---------------------------------------------------------------------------
// Chunked-parallel momentum EMA -> hi/lo bf16 A operand
// ---------------------------------------------------------------------------
__device__ __forceinline__ float mp_mean(const float* mp2, int i, int d) {
    const float inv = 1.0f / (float)PP;
    float s = mp2[(size_t)i * DD + d];
#pragma unroll
    for (int h = 1; h < SPLIT; h++) s += mp2[(size_t)(h * NF + i) * DD + d];
    return s * inv;
}
__global__ void k_ema(const float* __restrict__ mp2,
                      __nv_bfloat16* __restrict__ hiA, __nv_bfloat16* __restrict__ loA) {
    int bx = blockIdx.x;
    int d = (bx >> 3) * 256 + threadIdx.x;
    int c = bx & 7;
    int s = c * 16;
    int w = s - 26; if (w < 0) w = 0;
    int e_end = min(s + 16, NM1);
    float prev = mp_mean(mp2, w, d);
    float e = 0.f;
    for (int i = w; i < e_end; i++) {
        float cur = mp_mean(mp2, i + 1, d);
        float diff = cur - prev;
        e = (i == w) ? diff : (0.5f * diff + 0.5f * e);
        if (i >= s) {
            __nv_bfloat16 h, l;
            split_bf16(e, h, l);
            hiA[(size_t)i * DD + d] = h;
            loA[(size_t)i * DD + d] = l;
        }
        prev = cur;
    }
    if (c == 7) {
        hiA[(size_t)NM1 * DD + d] = __float2bfloat16(0.f);
        loA[(size_t)NM1 * DD + d] = __float2bfloat16(0.f);
    }
}

// ---------------------------------------------------------------------------
// Zero fill / bias init
// ---------------------------------------------------------------------------
__global__ void k_zero(float* __restrict__ C, int total) {
    int idx = blockIdx.x * 256 + threadIdx.x;
    if (idx < total) C[idx] = 0.f;
}
__global__ void k_init_bias(float* __restrict__ C, const float* __restrict__ bias,
                            int total, int Nn) {
    int idx = blockIdx.x * 256 + threadIdx.x;
    if (idx < total) C[idx] = bias[idx % Nn];
}

// ---------------------------------------------------------------------------
// Pipelined bf16 mma.sync GEMM, fused fp32->hi/lo B conversion, 3-term split.
// A smem [m][k] ASTR=40 (ldmatrix), B smem [k][n] NSTR=72 (ldmatrix.trans).
// BK=32, 2-stage cp.async pipeline for A, reg-prefetch + convert for B.
// CTA: 256 thr = 8 warps (4M x 2N); tile M=128 x N=64; split-K atomics.
// ---------------------------------------------------------------------------
#define BK   32
#define ASTR 40
#define NSTR 72
#define A_ST (128 * ASTR)
#define B_ST (BK * NSTR)
#define GEMM_SMEM ((4 * A_ST + 4 * B_ST) * 2)

__global__ __launch_bounds__(256, 2)
void k_gemm_fused(const __nv_bfloat16* __restrict__ hiA, const __nv_bfloat16* __restrict__ loA,
                  const float* __restrict__ B,
                  float* __restrict__ C, int M, int Ntot, int Kcta) {
    extern __shared__ __align__(16) unsigned char dyn[];
    __nv_bfloat16* Ahs[2];
    __nv_bfloat16* Als[2];
    __nv_bfloat16* Bhs[2];
    __nv_bfloat16* Bls[2];
    {
        __nv_bfloat16* p = reinterpret_cast<__nv_bfloat16*>(dyn);
        Ahs[0] = p;               Als[0] = Ahs[0] + A_ST;
        Ahs[1] = Als[0] + A_ST;   Als[1] = Ahs[1] + A_ST;
        Bhs[0] = Als[1] + A_ST;   Bls[0] = Bhs[0] + B_ST;
        Bhs[1] = Bls[0] + B_ST;   Bls[1] = Bhs[1] + B_ST;
    }

    const int tid = threadIdx.x;
    const int lane = tid & 31, wid = tid >> 5;
    const int wm = wid & 3, wn = wid >> 2;
    const int gid = lane >> 2, qd = lane & 3;
    const int n0 = blockIdx.x * 64;
    const int kb = blockIdx.z * Kcta;
    const int fr = lane & 15, fc = (lane >> 4) << 3;   // ldmatrix row/col select

    float acc[2][4][4];
#pragma unroll
    for (int i = 0; i < 2; i++)
#pragma unroll
        for (int j = 0; j < 4; j++)
#pragma unroll
            for (int q = 0; q < 4; q++) acc[i][j][q] = 0.f;

    const int a_r = tid >> 2, a_q = tid & 3;
    float4 breg[2];

    auto loadA = [&](int kc, int s) {
#pragma unroll
        for (int it = 0; it < 2; it++) {
            int r = a_r + it * 64;
            cpa16((uint32_t)__cvta_generic_to_shared(Ahs[s] + r * ASTR + a_q * 8),
                  hiA + (size_t)r * DD + kc + a_q * 8);
            cpa16((uint32_t)__cvta_generic_to_shared(Als[s] + r * ASTR + a_q * 8),
                  loA + (size_t)r * DD + kc + a_q * 8);
        }
        asm volatile("cp.async.commit_group;" ::: "memory");
    };
    auto loadBreg = [&](int kc) {
#pragma unroll
        for (int it = 0; it < 2; it++) {
            int k = (tid >> 4) + it * 16, nq = tid & 15;
            breg[it] = *reinterpret_cast<const float4*>(B + (size_t)(kc + k) * Ntot + n0 + nq * 4);
        }
    };
    auto storeB = [&](int s) {
#pragma unroll
        for (int it = 0; it < 2; it++) {
            int k = (tid >> 4) + it * 16, nq = tid & 15;
            float vals[4] = {breg[it].x, breg[it].y, breg[it].z, breg[it].w};
            __nv_bfloat16 h[4], l[4];
#pragma unroll
            for (int j = 0; j < 4; j++) split_bf16(vals[j], h[j], l[j]);
            __nv_bfloat162 h01 = __halves2bfloat162(h[0], h[1]);
            __nv_bfloat162 h23 = __halves2bfloat162(h[2], h[3]);
            __nv_bfloat162 l01 = __halves2bfloat162(l[0], l[1]);
            __nv_bfloat162 l23 = __halves2bfloat162(l[2], l[3]);
            uint2 uh, ul;
            uh.x = *reinterpret_cast<uint32_t*>(&h01); uh.y = *reinterpret_cast<uint32_t*>(&h23);
            ul.x = *reinterpret_cast<uint32_t*>(&l01); ul.y = *reinterpret_cast<uint32_t*>(&l23);
            *reinterpret_cast<uint2*>(&Bhs[s][k * NSTR + nq * 4]) = uh;
            *reinterpret_cast<uint2*>(&Bls[s][k * NSTR + nq * 4]) = ul;
        }
    };
    auto compute = [&](int s) {
        const __nv_bfloat16* Ah = Ahs[s];
        const __nv_bfloat16* Al = Als[s];
        const __nv_bfloat16* Bh = Bhs[s];
        const __nv_bfloat16* Bl = Bls[s];
#pragma unroll
        for (int ks = 0; ks < 2; ks++) {
            uint32_t ah[2][4], al[2][4], bh[4][2], bl[4][2];
#pragma unroll
            for (int mt = 0; mt < 2; mt++) {
                const __nv_bfloat16* pa = Ah + (wm * 32 + mt * 16 + fr) * ASTR + ks * 16 + fc;
                ldsm_x4(ah[mt], (uint32_t)__cvta_generic_to_shared(pa));
                const __nv_bfloat16* pl = Al + (wm * 32 + mt * 16 + fr) * ASTR + ks * 16 + fc;
                ldsm_x4(al[mt], (uint32_t)__cvta_generic_to_shared(pl));
            }
#pragma unroll
            for (int ntp = 0; ntp < 2; ntp++) {
                uint32_t r[4];
                const __nv_bfloat16* pb = Bh + (ks * 16 + fr) * NSTR + wn * 32 + ntp * 16 + fc;
                ldsm_x4t(r, (uint32_t)__cvta_generic_to_shared(pb));
                bh[2 * ntp][0] = r[0]; bh[2 * ntp][1] = r[1];
                bh[2 * ntp + 1][0] = r[2]; bh[2 * ntp + 1][1] = r[3];
                const __nv_bfloat16* pbl = Bl + (ks * 16 + fr) * NSTR + wn * 32 + ntp * 16 + fc;
                ldsm_x4t(r, (uint32_t)__cvta_generic_to_shared(pbl));
                bl[2 * ntp][0] = r[0]; bl[2 * ntp][1] = r[1];
                bl[2 * ntp + 1][0] = r[2]; bl[2 * ntp + 1][1] = r[3];
            }
#pragma unroll
            for (int mt = 0; mt < 2; mt++)
#pragma unroll
                for (int nt = 0; nt < 4; nt++) {
                    asm volatile(
                        "mma.sync.aligned.m16n8k16.row.col.f32.bf16.bf16.f32 "
                        "{%0,%1,%2,%3}, {%4,%5,%6,%7}, {%8,%9}, {%0,%1,%2,%3};"
                        : "+f"(acc[mt][nt][0]), "+f"(acc[mt][nt][1]),
                          "+f"(acc[mt][nt][2]), "+f"(acc[mt][nt][3])
                        : "r"(ah[mt][0]), "r"(ah[mt][1]), "r"(ah[mt][2]), "r"(ah[mt][3]),
                          "r"(bh[nt][0]), "r"(bh[nt][1]));
                    asm volatile(
                        "mma.sync.aligned.m16n8k16.row.col.f32.bf16.bf16.f32 "
                        "{%0,%1,%2,%3}, {%4,%5,%6,%7}, {%8,%9}, {%0,%1,%2,%3};"
                        : "+f"(acc[mt][nt][0]), "+f"(acc[mt][nt][1]),
                          "+f"(acc[mt][nt][2]), "+f"(acc[mt][nt][3])
                        : "r"(al[mt][0]), "r"(al[mt][1]), "r"(al[mt][2]), "r"(al[mt][3]),
                          "r"(bh[nt][0]), "r"(bh[nt][1]));
                    asm volatile(
                        "mma.sync.aligned.m16n8k16.row.col.f32.bf16.bf16.f32 "
                        "{%0,%1,%2,%3}, {%4,%5,%6,%7}, {%8,%9}, {%0,%1,%2,%3};"
                        : "+f"(acc[mt][nt][0]), "+f"(acc[mt][nt][1]),
                          "+f"(acc[mt][nt][2]), "+f"(acc[mt][nt][3])
                        : "r"(ah[mt][0]), "r"(ah[mt][1]), "r"(ah[mt][2]), "r"(ah[mt][3]),
                          "r"(bl[nt][0]), "r"(bl[nt][1]));
                }
        }
    };

    loadA(kb, 0);
    loadBreg(kb);
    storeB(0);
    asm volatile("cp.async.wait_group 0;" ::: "memory");
    __syncthreads();

    int cur = 0;
    for (int kc = kb; kc < kb + Kcta; kc += BK) {
        bool has = (kc + BK) < (kb + Kcta);
        if (has) {
            loadA(kc + BK, cur ^ 1);
            loadBreg(kc + BK);
        }
        compute(cur);
        if (has) {
            storeB(cur ^ 1);
            asm volatile("cp.async.wait_group 0;" ::: "memory");
            __syncthreads();
        }
        cur ^= 1;
    }

#pragma unroll
    for (int mt = 0; mt < 2; mt++) {
        int r0 = wm * 32 + mt * 16 + gid;
#pragma unroll
        for (int nt = 0; nt < 4; nt++) {
            int cc = n0 + wn * 32 + nt * 8 + qd * 2;
            if (r0 < M) {
                atomicAdd(&C[(size_t)r0 * Ntot + cc],     acc[mt][nt][0]);
                atomicAdd(&C[(size_t)r0 * Ntot + cc + 1], acc[mt][nt][1]);
            }
            if (r0 + 8 < M) {
                atomicAdd(&C[(size_t)(r0 + 8) * Ntot + cc],     acc[mt][nt][2]);
                atomicAdd(&C[(size_t)(r0 + 8) * Ntot + cc + 1], acc[mt][nt][3]);
            }
        }
    }
}

// ---------------------------------------------------------------------------
// LayerNorm per row (adds deferred bias badd) -> hi/lo bf16.
// ---------------------------------------------------------------------------
__global__ void k_ln(const float* __restrict__ X, const float* __restrict__ badd,
                     __nv_bfloat16* __restrict__ hiA, __nv_bfloat16* __restrict__ loA,
                     const float* __restrict__ gam, const float* __restrict__ bet) {
    int m = blockIdx.x;
    if (m == NM1) {
        for (int d = threadIdx.x; d < DD; d += 256) {
            hiA[(size_t)m * DD + d] = __float2bfloat16(0.f);
            loA[(size_t)m * DD + d] = __float2bfloat16(0.f);
        }
        return;
    }
    const float* x = X + (size_t)m * DD;
    __shared__ float red[32];
    __shared__ float s_mu, s_rstd;

    float s = 0.f;
    for (int d = threadIdx.x; d < DD; d += 256) s += x[d] + badd[d];
    for (int o = 16; o; o >>= 1) s += __shfl_down_sync(0xffffffffu, s, o);
    int w = threadIdx.x >> 5, lane = threadIdx.x & 31;
    if (lane == 0) red[w] = s;
    __syncthreads();
    if (threadIdx.x == 0) {
        float t = 0.f;
        for (int i = 0; i < 8; i++) t += red[i];
        s_mu = t / (float)DD;
    }
    __syncthreads();
    float mu = s_mu;

    float s2 = 0.f;
    for (int d = threadIdx.x; d < DD; d += 256) {
        float v = x[d] + badd[d] - mu; s2 += v * v;
    }
    for (int o = 16; o; o >>= 1) s2 += __shfl_down_sync(0xffffffffu, s2, o);
    if (lane == 0) red[w] = s2;
    __syncthreads();
    if (threadIdx.x == 0) {
        float t = 0.f;
        for (int i = 0; i < 8; i++) t += red[i];
        s_rstd = rsqrtf(t / (float)DD + 1e-5f);
    }
    __syncthreads();
    float rstd = s_rstd;

    for (int d = threadIdx.x; d < DD; d += 256) {
        float yv = (x[d] + badd[d] - mu) * rstd * gam[d] + bet[d];
        __nv_bfloat16 h, l;
        split_bf16(yv, h, l);
        hiA[(size_t)m * DD + d] = h;
        loA[(size_t)m * DD + d] = l;
    }
}

// ---------------------------------------------------------------------------
// Gate head: adds deferred bias b1, exact GELU, W2 matvec, Gumbel softmax y
// ---------------------------------------------------------------------------
__global__ void k_gate(const float* __restrict__ H, const float* __restrict__ b1,
                       const float* __restrict__ W2,
                       const float* __restrict__ b2, const float* __restrict__ gu,
                       float* __restrict__ out_gate, float* __restrict__ y) {
    int m = blockIdx.x;
    const float* h = H + (size_t)m * DD;
    float a0 = 0.f, a1 = 0.f;
    for (int k = threadIdx.x; k < DD; k += 128) {
        float hr = h[k] + b1[k];
        float hv = 0.5f * hr * (1.f + erff(hr * 0.70710678118654752440f));
        a0 += hv * W2[2 * k + 0];
        a1 += hv * W2[2 * k + 1];
    }
    for (int o = 16; o; o >>= 1) {
        a0 += __shfl_down_sync(0xffffffffu, a0, o);
        a1 += __shfl_down_sync(0xffffffffu, a1, o);
    }
    __shared__ float r0[4], r1[4];
    int w = threadIdx.x >> 5, lane = threadIdx.x & 31;
    if (lane == 0) { r0[w] = a0; r1[w] = a1; }
    __syncthreads();
    if (threadIdx.x == 0) {
        float l0 = r0[0] + r0[1] + r0[2] + r0[3] + b2[0];
        float l1 = r1[0] + r1[1] + r1[2] + r1[3] + b2[1];
        out_gate[2 * m + 0] = l0;
        out_gate[2 * m + 1] = l1;
        float u0 = gu[2 * m + 0], u1 = gu[2 * m + 1];
        float g0 = -logf(-logf(u0 + 1e-20f) + 1e-20f);
        float g1 = -logf(-logf(u1 + 1e-20f) + 1e-20f);
        float s0 = (l0 + 0.1f * g0) * 2.0f;
        float s1 = (l1 + 0.1f * g1) * 2.0f;
        y[m] = 1.0f / (1.0f + expf(s0 - s1));
    }
}

// ---------------------------------------------------------------------------
// Parallel top-8 of 127 + z_hard + selection list
// ---------------------------------------------------------------------------
__global__ void k_topk(const float* __restrict__ y, float* __restrict__ out_z) {
    __shared__ float sv[128];
    __shared__ int   si[128];
    int tid = threadIdx.x;
    float val = (tid < NM1) ? y[tid] : -1e30f;
    if (tid == 0) { out_z[0] = 1.f; g_sel[0] = 0; }
    if (tid < NM1) out_z[tid + 1] = 0.f;
    __syncthreads();
    for (int r = 0; r < NC; r++) {
        sv[tid] = val; si[tid] = tid;
        __syncthreads();
        for (int o = 64; o; o >>= 1) {
            if (tid < o) {
                float ov = sv[tid + o]; int oi = si[tid + o];
                if (ov > sv[tid] || (ov == sv[tid] && oi < si[tid])) {
                    sv[tid] = ov; si[tid] = oi;
                }
            }
            __syncthreads();
        }
        int wn = si[0];
        if (tid == wn) val = -1e30f;
        if (tid == 0) { g_sel[r + 1] = wn + 1; out_z[wn + 1] = 1.f; }
        __syncthreads();
    }
}

// ---------------------------------------------------------------------------
// Pooled thumbnail features -> hi/lo bf16 rows 0..63; pad rows 64..127
// ---------------------------------------------------------------------------
__global__ void k_pool(const float* __restrict__ v,
                       __nv_bfloat16* __restrict__ hiA, __nv_bfloat16* __restrict__ loA) {
    int b = blockIdx.x;
    if (b >= NQk * 3) {
        int b2 = b - NQk * 3;
        int q = NQk + b2 / 3, c = b2 % 3;
        int d = c * 512 + threadIdx.x * 4;
        for (int j = 0; j < 4; j++) {
            hiA[(size_t)q * DD + d + j] = __float2bfloat16(0.f);
            loA[(size_t)q * DD + d + j] = __float2bfloat16(0.f);
        }
        return;
    }
    int q = b / 3, c = b % 3;
    int d = c * 512 + threadIdx.x * 4;
    float ax = 0.f, ay = 0.f, az = 0.f, aw = 0.f;
    for (int s = 0; s <= NC; s++) {
        int f = g_sel[s];
        const float* base = v + ((size_t)f * PP + q * 9) * DD + d;
#pragma unroll
        for (int p = 0; p < 9; p++) {
            float4 x = *reinterpret_cast<const float4*>(base + (size_t)p * DD);
            ax += x.x; ay += x.y; az += x.z; aw += x.w;
        }
    }
    const float inv = 1.0f / 81.0f;
    float vals[4] = {ax * inv, ay * inv, az * inv, aw * inv};
#pragma unroll
    for (int j = 0; j < 4; j++) {
        __nv_bfloat16 h, l;
        split_bf16(vals[j], h, l);
        hiA[(size_t)q * DD + d + j] = h;
        loA[(size_t)q * DD + d + j] = l;
    }
}

// ---------------------------------------------------------------------------
// Launch
// ---------------------------------------------------------------------------
extern "C" void kernel_launch(void* const* d_in, const int* in_sizes, int n_in,
                              void* d_out, int out_size) {
    const float* v     = (const float*)d_in[0];
    const float* gu    = (const float*)d_in[1];
    const float* W_agg = (const float*)d_in[2];
    const float* b_agg = (const float*)d_in[3];
    const float* ln_g  = (const float*)d_in[4];
    const float* ln_b  = (const float*)d_in[5];
    const float* W1    = (const float*)d_in[6];
    const float* b1    = (const float*)d_in[7];
    const float* W2    = (const float*)d_in[8];
    const float* b2    = (const float*)d_in[9];
    const float* W_th  = (const float*)d_in[10];
    const float* b_th  = (const float*)d_in[11];

    float* out       = (float*)d_out;
    float* out_gate  = out;
    float* out_thumb = out + NM1 * 2;
    float* out_z     = out_thumb + NQk * LMq;

    float* scr = nullptr;
    cudaGetSymbolAddress((void**)&scr, g_scratch);
    float* mp2  = scr + OFF_MP;
    float* feat = scr + OFF_FEAT;
    float* h    = scr + OFF_H;
    float* yv   = scr + OFF_Y;

    __nv_bfloat16 *hiA, *loA;
    cudaGetSymbolAddress((void**)&hiA, g_hiA);
    cudaGetSymbolAddress((void**)&loA, g_loA);

    cudaFuncSetAttribute(k_gemm_fused, cudaFuncAttributeMaxDynamicSharedMemorySize, GEMM_SMEM);

    // Zero feat+h accumulators (contiguous), patch sums, EMA
    k_zero<<<(2 * NM1 * DD + 255) / 256, 256>>>(feat, 2 * NM1 * DD);
    k_mp<<<NF * 3 * SPLIT, 128>>>(v, mp2);
    k_ema<<<(DD / 256) * 8, 256>>>(mp2, hiA, loA);

    // GEMM1: feat = ema @ W_agg   (b_agg folded into k_ln)
    {
        dim3 grid(DD / 64, 1, 12);
        k_gemm_fused<<<grid, 256, GEMM_SMEM>>>(hiA, loA, W_agg, feat, NM1, DD, DD / 12);
    }

    // LayerNorm (adds b_agg, emits hi/lo A)
    k_ln<<<NM1 + 1, 256>>>(feat, b_agg, hiA, loA, ln_g, ln_b);

    // GEMM2: h = xn @ W1   (b1 folded into k_gate)
    {
        dim3 grid(DD / 64, 1, 12);
        k_gemm_fused<<<grid, 256, GEMM_SMEM>>>(hiA, loA, W1, h, NM1, DD, DD / 12);
    }

    // gate + topk + pool
    k_gate<<<NM1, 128>>>(h, b1, W2, b2, gu, out_gate, yv);
    k_topk<<<1, 128>>>(yv, out_z);
    k_pool<<<NQk * 3 * 2, 128>>>(v, hiA, loA);

    // GEMM3: thumbnail = pooled @ W_th + b_th
    k_init_bias<<<(NQk * LMq + 255) / 256, 256>>>(out_thumb, b_th, NQk * LMq, LMq);
    {
        dim3 grid(LMq / 64, 1, 6);
        k_gemm_fused<<<grid, 256, GEMM_SMEM>>>(hiA, loA, W_th, out_thumb, NQk, LMq, DD / 6);
    }
}